// round 1
// baseline (speedup 1.0000x reference)
#include <cuda_runtime.h>
#include <math.h>

#define DM 2048
#define NH 16
#define HD 128
#define BB 2
#define SSEQ 2048
#define MTOK 4096

#define PROJ_SZ (8388608UL)            // 4096*2048
#define SCORE_SZ (134217728UL)         // 2*16*2048*2048
#define OFF_Q1 (0UL)
#define OFF_K1 (1UL*PROJ_SZ)
#define OFF_Q2 (2UL*PROJ_SZ)
#define OFF_K2 (3UL*PROJ_SZ)
#define OFF_V  (4UL*PROJ_SZ)
#define OFF_HO (5UL*PROJ_SZ)
#define OFF_S1 (6UL*PROJ_SZ)
#define OFF_S2 (OFF_S1 + SCORE_SZ)
#define SCRATCH_FLOATS (OFF_S2 + SCORE_SZ)

__device__ float g_scratch[SCRATCH_FLOATS];

// ---------------------------------------------------------------------------
// C[M,N] = alpha * A[M,K] * B[N,K]^T   (both operands K-major, "NT")
// 128x128 block tile, BK=8, 256 threads, 8x8 register microtile.
// Batched over blockIdx.z with (b,h)-decomposed strides.
// A/B/C may be external pointers (non-null) or offsets into g_scratch (null ptr).
// ---------------------------------------------------------------------------
__global__ void __launch_bounds__(256) gemm_nt(
    const float* __restrict__ A, size_t offA,
    const float* __restrict__ Bm, size_t offB,
    float* __restrict__ C, size_t offC,
    int K, int lda, int ldb, int ldc, float alpha,
    long long sAb, long long sAh, long long sBb, long long sBh,
    long long sCb, long long sCh)
{
    const float* Ap = A ? A : (const float*)(g_scratch + offA);
    const float* Bp = Bm ? Bm : (const float*)(g_scratch + offB);
    float*       Cp = C ? C : (g_scratch + offC);
    int zb = blockIdx.z / NH, zh = blockIdx.z % NH;
    Ap += (size_t)zb * sAb + (size_t)zh * sAh;
    Bp += (size_t)zb * sBb + (size_t)zh * sBh;
    Cp += (size_t)zb * sCb + (size_t)zh * sCh;

    __shared__ float As[8][128];
    __shared__ float Bs[8][128];

    int tid  = threadIdx.x;
    int lrow = tid >> 1;            // 0..127
    int kq   = (tid & 1) << 2;      // 0 or 4
    const float* aGlb = Ap + (size_t)(blockIdx.y * 128 + lrow) * lda + kq;
    const float* bGlb = Bp + (size_t)(blockIdx.x * 128 + lrow) * ldb + kq;

    int ty = tid >> 4, tx = tid & 15;

    float acc[8][8];
#pragma unroll
    for (int i = 0; i < 8; i++)
#pragma unroll
        for (int j = 0; j < 8; j++) acc[i][j] = 0.f;

    int nk = K >> 3;
    for (int kt = 0; kt < nk; ++kt) {
        float4 av = *(const float4*)aGlb;
        float4 bv = *(const float4*)bGlb;
        As[kq + 0][lrow] = av.x; As[kq + 1][lrow] = av.y;
        As[kq + 2][lrow] = av.z; As[kq + 3][lrow] = av.w;
        Bs[kq + 0][lrow] = bv.x; Bs[kq + 1][lrow] = bv.y;
        Bs[kq + 2][lrow] = bv.z; Bs[kq + 3][lrow] = bv.w;
        __syncthreads();
#pragma unroll
        for (int k = 0; k < 8; k++) {
            float a[8], b[8];
#pragma unroll
            for (int i = 0; i < 8; i++) a[i] = As[k][ty * 8 + i];
#pragma unroll
            for (int j = 0; j < 8; j++) b[j] = Bs[k][tx * 8 + j];
#pragma unroll
            for (int i = 0; i < 8; i++)
#pragma unroll
                for (int j = 0; j < 8; j++)
                    acc[i][j] = fmaf(a[i], b[j], acc[i][j]);
        }
        __syncthreads();
        aGlb += 8; bGlb += 8;
    }

#pragma unroll
    for (int i = 0; i < 8; i++) {
        float* crow = Cp + (size_t)(blockIdx.y * 128 + ty * 8 + i) * ldc
                         + blockIdx.x * 128 + tx * 8;
        float4 v0 = make_float4(alpha * acc[i][0], alpha * acc[i][1],
                                alpha * acc[i][2], alpha * acc[i][3]);
        float4 v1 = make_float4(alpha * acc[i][4], alpha * acc[i][5],
                                alpha * acc[i][6], alpha * acc[i][7]);
        *(float4*)crow = v0;
        *(float4*)(crow + 4) = v1;
    }
}

// ---------------------------------------------------------------------------
// C[M,N] = alpha * A[M,K] * B[K,N]   ("NN") — used for P @ V.
// ---------------------------------------------------------------------------
__global__ void __launch_bounds__(256) gemm_nn(
    const float* __restrict__ A, size_t offA,
    const float* __restrict__ Bm, size_t offB,
    float* __restrict__ C, size_t offC,
    int K, int lda, int ldb, int ldc, float alpha,
    long long sAb, long long sAh, long long sBb, long long sBh,
    long long sCb, long long sCh)
{
    const float* Ap = A ? A : (const float*)(g_scratch + offA);
    const float* Bp = Bm ? Bm : (const float*)(g_scratch + offB);
    float*       Cp = C ? C : (g_scratch + offC);
    int zb = blockIdx.z / NH, zh = blockIdx.z % NH;
    Ap += (size_t)zb * sAb + (size_t)zh * sAh;
    Bp += (size_t)zb * sBb + (size_t)zh * sBh;
    Cp += (size_t)zb * sCb + (size_t)zh * sCh;

    __shared__ float As[8][128];
    __shared__ float Bs[8][128];

    int tid  = threadIdx.x;
    int lrow = tid >> 1;
    int kq   = (tid & 1) << 2;
    const float* aGlb = Ap + (size_t)(blockIdx.y * 128 + lrow) * lda + kq;

    int bk = tid >> 5;              // 0..7
    int bn = (tid & 31) << 2;       // 0..124
    const float* bGlb = Bp + (size_t)bk * ldb + blockIdx.x * 128 + bn;

    int ty = tid >> 4, tx = tid & 15;

    float acc[8][8];
#pragma unroll
    for (int i = 0; i < 8; i++)
#pragma unroll
        for (int j = 0; j < 8; j++) acc[i][j] = 0.f;

    int nk = K >> 3;
    for (int kt = 0; kt < nk; ++kt) {
        float4 av = *(const float4*)aGlb;
        float4 bv = *(const float4*)bGlb;
        As[kq + 0][lrow] = av.x; As[kq + 1][lrow] = av.y;
        As[kq + 2][lrow] = av.z; As[kq + 3][lrow] = av.w;
        *(float4*)&Bs[bk][bn] = bv;
        __syncthreads();
#pragma unroll
        for (int k = 0; k < 8; k++) {
            float a[8], b[8];
#pragma unroll
            for (int i = 0; i < 8; i++) a[i] = As[k][ty * 8 + i];
#pragma unroll
            for (int j = 0; j < 8; j++) b[j] = Bs[k][tx * 8 + j];
#pragma unroll
            for (int i = 0; i < 8; i++)
#pragma unroll
                for (int j = 0; j < 8; j++)
                    acc[i][j] = fmaf(a[i], b[j], acc[i][j]);
        }
        __syncthreads();
        aGlb += 8;
        bGlb += (size_t)8 * ldb;
    }

#pragma unroll
    for (int i = 0; i < 8; i++) {
        float* crow = Cp + (size_t)(blockIdx.y * 128 + ty * 8 + i) * ldc
                         + blockIdx.x * 128 + tx * 8;
        float4 v0 = make_float4(alpha * acc[i][0], alpha * acc[i][1],
                                alpha * acc[i][2], alpha * acc[i][3]);
        float4 v1 = make_float4(alpha * acc[i][4], alpha * acc[i][5],
                                alpha * acc[i][6], alpha * acc[i][7]);
        *(float4*)crow = v0;
        *(float4*)(crow + 4) = v1;
    }
}

// ---------------------------------------------------------------------------
// Row-wise: P = softmax(S1_row) - lambda[h] * softmax(S2_row), written into S1.
// One block (256 thr) per row of length 2048; 8 elems/thread/matrix in regs.
// ---------------------------------------------------------------------------
__global__ void __launch_bounds__(256) softmax_combine(const float* __restrict__ lam)
{
    int r = blockIdx.x;                  // 0 .. B*H*S-1
    int h = (r / SSEQ) % NH;
    float lamh = lam[h];
    float* p1 = g_scratch + OFF_S1 + (size_t)r * SSEQ;
    float* p2 = g_scratch + OFF_S2 + (size_t)r * SSEQ;
    int t = threadIdx.x;

    float x1[8], x2[8];
#pragma unroll
    for (int i = 0; i < 8; i++) {
        x1[i] = p1[t + i * 256];
        x2[i] = p2[t + i * 256];
    }

    float m1 = -1e30f, m2 = -1e30f;
#pragma unroll
    for (int i = 0; i < 8; i++) {
        m1 = fmaxf(m1, x1[i]);
        m2 = fmaxf(m2, x2[i]);
    }
#pragma unroll
    for (int o = 16; o > 0; o >>= 1) {
        m1 = fmaxf(m1, __shfl_xor_sync(0xffffffffu, m1, o));
        m2 = fmaxf(m2, __shfl_xor_sync(0xffffffffu, m2, o));
    }
    __shared__ float sa[8], sb[8];
    int wid = t >> 5, lane = t & 31;
    if (lane == 0) { sa[wid] = m1; sb[wid] = m2; }
    __syncthreads();
    m1 = sa[0]; m2 = sb[0];
#pragma unroll
    for (int w = 1; w < 8; w++) {
        m1 = fmaxf(m1, sa[w]);
        m2 = fmaxf(m2, sb[w]);
    }
    __syncthreads();

    float e1 = 0.f, e2 = 0.f;
#pragma unroll
    for (int i = 0; i < 8; i++) {
        x1[i] = __expf(x1[i] - m1); e1 += x1[i];
        x2[i] = __expf(x2[i] - m2); e2 += x2[i];
    }
#pragma unroll
    for (int o = 16; o > 0; o >>= 1) {
        e1 += __shfl_xor_sync(0xffffffffu, e1, o);
        e2 += __shfl_xor_sync(0xffffffffu, e2, o);
    }
    if (lane == 0) { sa[wid] = e1; sb[wid] = e2; }
    __syncthreads();
    e1 = 0.f; e2 = 0.f;
#pragma unroll
    for (int w = 0; w < 8; w++) { e1 += sa[w]; e2 += sb[w]; }

    float i1 = 1.f / e1;
    float i2 = lamh / e2;
#pragma unroll
    for (int i = 0; i < 8; i++)
        p1[t + i * 256] = x1[i] * i1 - x2[i] * i2;
}

// ---------------------------------------------------------------------------
extern "C" void kernel_launch(void* const* d_in, const int* in_sizes, int n_in,
                              void* d_out, int out_size)
{
    const float* x   = (const float*)d_in[0];
    const float* wq1 = (const float*)d_in[1];
    const float* wk1 = (const float*)d_in[2];
    const float* wq2 = (const float*)d_in[3];
    const float* wk2 = (const float*)d_in[4];
    const float* wv  = (const float*)d_in[5];
    const float* wo  = (const float*)d_in[6];
    const float* lam = (const float*)d_in[7];
    float* out = (float*)d_out;

    dim3 blk(256);

    // 1) Projections: [4096,2048] @ W^T -> scratch
    dim3 gProj(16, 32, 1);
    gemm_nt<<<gProj, blk>>>(x, 0, wq1, 0, nullptr, OFF_Q1, DM, DM, DM, DM, 1.f, 0,0,0,0,0,0);
    gemm_nt<<<gProj, blk>>>(x, 0, wk1, 0, nullptr, OFF_K1, DM, DM, DM, DM, 1.f, 0,0,0,0,0,0);
    gemm_nt<<<gProj, blk>>>(x, 0, wq2, 0, nullptr, OFF_Q2, DM, DM, DM, DM, 1.f, 0,0,0,0,0,0);
    gemm_nt<<<gProj, blk>>>(x, 0, wk2, 0, nullptr, OFF_K2, DM, DM, DM, DM, 1.f, 0,0,0,0,0,0);
    gemm_nt<<<gProj, blk>>>(x, 0, wv,  0, nullptr, OFF_V,  DM, DM, DM, DM, 1.f, 0,0,0,0,0,0);

    // 2) Batched QK^T for both attention branches (scaled by 1/sqrt(Dh))
    const float scl = 0.08838834764831845f;  // 1/sqrt(128)
    dim3 gQK(16, 16, BB * NH);
    long long sQb = (long long)SSEQ * DM, sQh = HD;
    long long sSb = (long long)NH * SSEQ * SSEQ, sSh = (long long)SSEQ * SSEQ;
    gemm_nt<<<gQK, blk>>>(nullptr, OFF_Q1, nullptr, OFF_K1, nullptr, OFF_S1,
                          HD, DM, DM, SSEQ, scl, sQb, sQh, sQb, sQh, sSb, sSh);
    gemm_nt<<<gQK, blk>>>(nullptr, OFF_Q2, nullptr, OFF_K2, nullptr, OFF_S2,
                          HD, DM, DM, SSEQ, scl, sQb, sQh, sQb, sQh, sSb, sSh);

    // 3) Fused dual softmax + differential combine (writes P into S1 buffer)
    softmax_combine<<<BB * NH * SSEQ, blk>>>(lam);

    // 4) Batched P @ V -> head-concat layout [4096, 2048]
    dim3 gPV(1, 16, BB * NH);
    gemm_nn<<<gPV, blk>>>(nullptr, OFF_S1, nullptr, OFF_V, nullptr, OFF_HO,
                          SSEQ, SSEQ, DM, DM, 1.f,
                          sSb, sSh, sQb, sQh, sQb, sQh);

    // 5) Output projection -> d_out
    dim3 gOut(16, 32, 1);
    gemm_nt<<<gOut, blk>>>(nullptr, OFF_HO, wo, 0, out, 0, DM, DM, DM, DM, 1.f, 0,0,0,0,0,0);
}

// round 2
// speedup vs baseline: 1.7949x; 1.7949x over previous
#include <cuda_runtime.h>
#include <math.h>
#include <stdint.h>

#define DM 2048
#define NH 16
#define HD 128
#define BB 2
#define SSEQ 2048

#define PROJ_SZ (8388608UL)            // 4096*2048
#define SCORE_SZ (134217728UL)         // 2*16*2048*2048
#define OFF_Q1 (0UL)
#define OFF_K1 (1UL*PROJ_SZ)
#define OFF_Q2 (2UL*PROJ_SZ)
#define OFF_K2 (3UL*PROJ_SZ)
#define OFF_V  (4UL*PROJ_SZ)
#define OFF_HO (5UL*PROJ_SZ)
#define OFF_S1 (6UL*PROJ_SZ)
#define OFF_S2 (OFF_S1 + SCORE_SZ)
#define SCRATCH_FLOATS (OFF_S2 + SCORE_SZ)

__device__ float g_scratch[SCRATCH_FLOATS];

#define BK 32
#define LDSR 36                         // padded row stride (floats)
#define TILE_F (128 * LDSR)             // floats per operand per stage
#define SMEM_BYTES (4 * TILE_F * 4)     // 2 operands x 2 stages x 4B = 73728

__device__ __forceinline__ uint32_t f2tf(float f) {
    uint32_t u;
    asm("cvt.rna.tf32.f32 %0, %1;" : "=r"(u) : "f"(f));
    return u;
}

__device__ __forceinline__ void mma8(float* c, const uint32_t* a, const uint32_t* b) {
    asm volatile(
        "mma.sync.aligned.m16n8k8.row.col.f32.tf32.tf32.f32 "
        "{%0,%1,%2,%3}, {%4,%5,%6,%7}, {%8,%9}, {%0,%1,%2,%3};"
        : "+f"(c[0]), "+f"(c[1]), "+f"(c[2]), "+f"(c[3])
        : "r"(a[0]), "r"(a[1]), "r"(a[2]), "r"(a[3]), "r"(b[0]), "r"(b[1]));
}

// ---------------------------------------------------------------------------
// C[M,N] = alpha * A[M,K] * op(B).  TRANSB=1: B is [N,K] row-major (NT).
// TRANSB=0: B is [K,N] row-major (NN).  128x128x32 tiles, tf32 mma.sync,
// register-staged double-buffered smem. A/B/C either external ptr or scratch
// offset; batched over blockIdx.z with (b,h) strides.
// ---------------------------------------------------------------------------
template <int TRANSB>
__global__ void __launch_bounds__(256) gemm_tf32(
    const float* __restrict__ A, size_t offA,
    const float* __restrict__ Bm, size_t offB,
    float* __restrict__ C, size_t offC,
    int K, int lda, int ldb, int ldc, float alpha,
    long long sAb, long long sAh, long long sBb, long long sBh,
    long long sCb, long long sCh)
{
    extern __shared__ float smem[];
    const float* Ap = A ? A : (const float*)(g_scratch + offA);
    const float* Bp = Bm ? Bm : (const float*)(g_scratch + offB);
    float*       Cp = C ? C : (g_scratch + offC);
    int zb = blockIdx.z / NH, zh = blockIdx.z % NH;
    Ap += (size_t)zb * sAb + (size_t)zh * sAh;
    Bp += (size_t)zb * sBb + (size_t)zh * sBh;
    Cp += (size_t)zb * sCb + (size_t)zh * sCh;

    uint32_t* sAbuf[2] = { (uint32_t*)smem,            (uint32_t*)smem + TILE_F };
    uint32_t* sBbuf[2] = { (uint32_t*)smem + 2*TILE_F, (uint32_t*)smem + 3*TILE_F };

    int tid  = threadIdx.x;
    int lane = tid & 31;
    int wid  = tid >> 5;
    int wm   = wid >> 2;        // 0..1  (64-row slab)
    int wn   = wid & 3;         // 0..3  (32-col slab)

    // staging coordinates
    int ar0 = tid >> 3;             // 0..31
    int ac0 = (tid & 7) << 2;       // 0..28
    const float* aBase = Ap + (size_t)(blockIdx.y * 128 + ar0) * lda + ac0;
    const float* bBase;
    int bn0 = 0, bk0 = 0;
    if (TRANSB) {
        bBase = Bp + (size_t)(blockIdx.x * 128 + ar0) * ldb + ac0;
    } else {
        bk0 = tid >> 5;             // 0..7
        bn0 = (tid & 31) << 2;      // 0..124
        bBase = Bp + (size_t)bk0 * ldb + blockIdx.x * 128 + bn0;
    }

    float acc[4][4][4];
#pragma unroll
    for (int mt = 0; mt < 4; mt++)
#pragma unroll
        for (int nt = 0; nt < 4; nt++)
#pragma unroll
            for (int i = 0; i < 4; i++) acc[mt][nt][i] = 0.f;

    float4 ar[4], br[4];

    // prologue: load tile 0
#pragma unroll
    for (int i = 0; i < 4; i++)
        ar[i] = *(const float4*)(aBase + (size_t)i * 32 * lda);
#pragma unroll
    for (int i = 0; i < 4; i++)
        br[i] = TRANSB ? *(const float4*)(bBase + (size_t)i * 32 * ldb)
                       : *(const float4*)(bBase + (size_t)i * 8 * ldb);

    int cur = 0;
    // stage tile 0
#pragma unroll
    for (int i = 0; i < 4; i++) {
        uint32_t* d = sAbuf[cur] + (ar0 + i * 32) * LDSR + ac0;
        d[0] = f2tf(ar[i].x); d[1] = f2tf(ar[i].y);
        d[2] = f2tf(ar[i].z); d[3] = f2tf(ar[i].w);
    }
    if (TRANSB) {
#pragma unroll
        for (int i = 0; i < 4; i++) {
            uint32_t* d = sBbuf[cur] + (ar0 + i * 32) * LDSR + ac0;
            d[0] = f2tf(br[i].x); d[1] = f2tf(br[i].y);
            d[2] = f2tf(br[i].z); d[3] = f2tf(br[i].w);
        }
    } else {
#pragma unroll
        for (int i = 0; i < 4; i++) {
            int k = bk0 + i * 8;
            uint32_t* d = sBbuf[cur] + bn0 * LDSR + k;
            d[0 * LDSR] = f2tf(br[i].x); d[1 * LDSR] = f2tf(br[i].y);
            d[2 * LDSR] = f2tf(br[i].z); d[3 * LDSR] = f2tf(br[i].w);
        }
    }
    __syncthreads();

    int nk = K >> 5;
    for (int kt = 0; kt < nk; ++kt) {
        bool more = (kt + 1) < nk;
        if (more) {
            aBase += BK;
#pragma unroll
            for (int i = 0; i < 4; i++)
                ar[i] = *(const float4*)(aBase + (size_t)i * 32 * lda);
            if (TRANSB) {
                bBase += BK;
#pragma unroll
                for (int i = 0; i < 4; i++)
                    br[i] = *(const float4*)(bBase + (size_t)i * 32 * ldb);
            } else {
                bBase += (size_t)BK * ldb;
#pragma unroll
                for (int i = 0; i < 4; i++)
                    br[i] = *(const float4*)(bBase + (size_t)i * 8 * ldb);
            }
        }

        const uint32_t* pa = sAbuf[cur];
        const uint32_t* pb = sBbuf[cur];
#pragma unroll
        for (int ks = 0; ks < 4; ks++) {
            int c = ks * 8 + (lane & 3);
            uint32_t af[4][4], bf[4][2];
#pragma unroll
            for (int mt = 0; mt < 4; mt++) {
                int r = wm * 64 + mt * 16 + (lane >> 2);
                af[mt][0] = pa[r * LDSR + c];
                af[mt][1] = pa[(r + 8) * LDSR + c];
                af[mt][2] = pa[r * LDSR + c + 4];
                af[mt][3] = pa[(r + 8) * LDSR + c + 4];
            }
#pragma unroll
            for (int nt = 0; nt < 4; nt++) {
                int n = wn * 32 + nt * 8 + (lane >> 2);
                bf[nt][0] = pb[n * LDSR + c];
                bf[nt][1] = pb[n * LDSR + c + 4];
            }
#pragma unroll
            for (int mt = 0; mt < 4; mt++)
#pragma unroll
                for (int nt = 0; nt < 4; nt++)
                    mma8(acc[mt][nt], af[mt], bf[nt]);
        }

        if (more) {
            cur ^= 1;
#pragma unroll
            for (int i = 0; i < 4; i++) {
                uint32_t* d = sAbuf[cur] + (ar0 + i * 32) * LDSR + ac0;
                d[0] = f2tf(ar[i].x); d[1] = f2tf(ar[i].y);
                d[2] = f2tf(ar[i].z); d[3] = f2tf(ar[i].w);
            }
            if (TRANSB) {
#pragma unroll
                for (int i = 0; i < 4; i++) {
                    uint32_t* d = sBbuf[cur] + (ar0 + i * 32) * LDSR + ac0;
                    d[0] = f2tf(br[i].x); d[1] = f2tf(br[i].y);
                    d[2] = f2tf(br[i].z); d[3] = f2tf(br[i].w);
                }
            } else {
#pragma unroll
                for (int i = 0; i < 4; i++) {
                    int k = bk0 + i * 8;
                    uint32_t* d = sBbuf[cur] + bn0 * LDSR + k;
                    d[0 * LDSR] = f2tf(br[i].x); d[1 * LDSR] = f2tf(br[i].y);
                    d[2 * LDSR] = f2tf(br[i].z); d[3 * LDSR] = f2tf(br[i].w);
                }
            }
            __syncthreads();
        }
    }

    // epilogue
#pragma unroll
    for (int mt = 0; mt < 4; mt++) {
        int r = blockIdx.y * 128 + wm * 64 + mt * 16 + (lane >> 2);
#pragma unroll
        for (int nt = 0; nt < 4; nt++) {
            int cc = blockIdx.x * 128 + wn * 32 + nt * 8 + ((lane & 3) << 1);
            float2 v0 = make_float2(alpha * acc[mt][nt][0], alpha * acc[mt][nt][1]);
            float2 v1 = make_float2(alpha * acc[mt][nt][2], alpha * acc[mt][nt][3]);
            *(float2*)&Cp[(size_t)r * ldc + cc]       = v0;
            *(float2*)&Cp[(size_t)(r + 8) * ldc + cc] = v1;
        }
    }
}

// ---------------------------------------------------------------------------
// Row-wise: P = softmax(S1_row) - lambda[h] * softmax(S2_row), written into S1.
// ---------------------------------------------------------------------------
__global__ void __launch_bounds__(256) softmax_combine(const float* __restrict__ lam)
{
    int r = blockIdx.x;
    int h = (r / SSEQ) % NH;
    float lamh = lam[h];
    float* p1 = g_scratch + OFF_S1 + (size_t)r * SSEQ;
    float* p2 = g_scratch + OFF_S2 + (size_t)r * SSEQ;
    int t = threadIdx.x;

    float x1[8], x2[8];
#pragma unroll
    for (int i = 0; i < 8; i++) {
        x1[i] = p1[t + i * 256];
        x2[i] = p2[t + i * 256];
    }

    float m1 = -1e30f, m2 = -1e30f;
#pragma unroll
    for (int i = 0; i < 8; i++) {
        m1 = fmaxf(m1, x1[i]);
        m2 = fmaxf(m2, x2[i]);
    }
#pragma unroll
    for (int o = 16; o > 0; o >>= 1) {
        m1 = fmaxf(m1, __shfl_xor_sync(0xffffffffu, m1, o));
        m2 = fmaxf(m2, __shfl_xor_sync(0xffffffffu, m2, o));
    }
    __shared__ float sa[8], sb[8];
    int wid = t >> 5, lane = t & 31;
    if (lane == 0) { sa[wid] = m1; sb[wid] = m2; }
    __syncthreads();
    m1 = sa[0]; m2 = sb[0];
#pragma unroll
    for (int w = 1; w < 8; w++) {
        m1 = fmaxf(m1, sa[w]);
        m2 = fmaxf(m2, sb[w]);
    }
    __syncthreads();

    float e1 = 0.f, e2 = 0.f;
#pragma unroll
    for (int i = 0; i < 8; i++) {
        x1[i] = __expf(x1[i] - m1); e1 += x1[i];
        x2[i] = __expf(x2[i] - m2); e2 += x2[i];
    }
#pragma unroll
    for (int o = 16; o > 0; o >>= 1) {
        e1 += __shfl_xor_sync(0xffffffffu, e1, o);
        e2 += __shfl_xor_sync(0xffffffffu, e2, o);
    }
    if (lane == 0) { sa[wid] = e1; sb[wid] = e2; }
    __syncthreads();
    e1 = 0.f; e2 = 0.f;
#pragma unroll
    for (int w = 0; w < 8; w++) { e1 += sa[w]; e2 += sb[w]; }

    float i1 = 1.f / e1;
    float i2 = lamh / e2;
#pragma unroll
    for (int i = 0; i < 8; i++)
        p1[t + i * 256] = x1[i] * i1 - x2[i] * i2;
}

// ---------------------------------------------------------------------------
extern "C" void kernel_launch(void* const* d_in, const int* in_sizes, int n_in,
                              void* d_out, int out_size)
{
    const float* x   = (const float*)d_in[0];
    const float* wq1 = (const float*)d_in[1];
    const float* wk1 = (const float*)d_in[2];
    const float* wq2 = (const float*)d_in[3];
    const float* wk2 = (const float*)d_in[4];
    const float* wv  = (const float*)d_in[5];
    const float* wo  = (const float*)d_in[6];
    const float* lam = (const float*)d_in[7];
    float* out = (float*)d_out;

    cudaFuncSetAttribute(gemm_tf32<1>, cudaFuncAttributeMaxDynamicSharedMemorySize, SMEM_BYTES);
    cudaFuncSetAttribute(gemm_tf32<0>, cudaFuncAttributeMaxDynamicSharedMemorySize, SMEM_BYTES);

    dim3 blk(256);

    // 1) Projections: [4096,2048] @ W^T -> scratch
    dim3 gProj(16, 32, 1);
    gemm_tf32<1><<<gProj, blk, SMEM_BYTES>>>(x, 0, wq1, 0, nullptr, OFF_Q1, DM, DM, DM, DM, 1.f, 0,0,0,0,0,0);
    gemm_tf32<1><<<gProj, blk, SMEM_BYTES>>>(x, 0, wk1, 0, nullptr, OFF_K1, DM, DM, DM, DM, 1.f, 0,0,0,0,0,0);
    gemm_tf32<1><<<gProj, blk, SMEM_BYTES>>>(x, 0, wq2, 0, nullptr, OFF_Q2, DM, DM, DM, DM, 1.f, 0,0,0,0,0,0);
    gemm_tf32<1><<<gProj, blk, SMEM_BYTES>>>(x, 0, wk2, 0, nullptr, OFF_K2, DM, DM, DM, DM, 1.f, 0,0,0,0,0,0);
    gemm_tf32<1><<<gProj, blk, SMEM_BYTES>>>(x, 0, wv,  0, nullptr, OFF_V,  DM, DM, DM, DM, 1.f, 0,0,0,0,0,0);

    // 2) Batched QK^T (scaled by 1/sqrt(Dh))
    const float scl = 0.08838834764831845f;
    dim3 gQK(16, 16, BB * NH);
    long long sQb = (long long)SSEQ * DM, sQh = HD;
    long long sSb = (long long)NH * SSEQ * SSEQ, sSh = (long long)SSEQ * SSEQ;
    gemm_tf32<1><<<gQK, blk, SMEM_BYTES>>>(nullptr, OFF_Q1, nullptr, OFF_K1, nullptr, OFF_S1,
                          HD, DM, DM, SSEQ, scl, sQb, sQh, sQb, sQh, sSb, sSh);
    gemm_tf32<1><<<gQK, blk, SMEM_BYTES>>>(nullptr, OFF_Q2, nullptr, OFF_K2, nullptr, OFF_S2,
                          HD, DM, DM, SSEQ, scl, sQb, sQh, sQb, sQh, sSb, sSh);

    // 3) Fused dual softmax + differential combine (writes P into S1 buffer)
    softmax_combine<<<BB * NH * SSEQ, blk>>>(lam);

    // 4) Batched P @ V -> head-concat layout [4096, 2048]
    dim3 gPV(1, 16, BB * NH);
    gemm_tf32<0><<<gPV, blk, SMEM_BYTES>>>(nullptr, OFF_S1, nullptr, OFF_V, nullptr, OFF_HO,
                          SSEQ, SSEQ, DM, DM, 1.f,
                          sSb, sSh, sQb, sQh, sQb, sQh);

    // 5) Output projection -> d_out
    dim3 gOut(16, 32, 1);
    gemm_tf32<1><<<gOut, blk, SMEM_BYTES>>>(nullptr, OFF_HO, wo, 0, out, 0, DM, DM, DM, DM, 1.f, 0,0,0,0,0,0);
}

// round 4
// speedup vs baseline: 4.0538x; 2.2585x over previous
#include <cuda_runtime.h>
#include <math.h>
#include <stdint.h>

#define DM 2048
#define NH 16
#define HD 128
#define BB 2
#define SSEQ 2048

#define PROJ_SZ (8388608UL)            // 4096*2048
#define W_SZ    (4194304UL)            // 2048*2048
#define SCORE_SZ (134217728UL)         // 32*2048*2048
#define OFF_Q1 (0UL)
#define OFF_K1 (1UL*PROJ_SZ)
#define OFF_Q2 (2UL*PROJ_SZ)
#define OFF_K2 (3UL*PROJ_SZ)
#define OFF_V  (4UL*PROJ_SZ)
#define OFF_HO (5UL*PROJ_SZ)
#define OFF_S1 (6UL*PROJ_SZ)
#define OFF_S2 (OFF_S1 + SCORE_SZ)
#define OFF_XR (OFF_S2 + SCORE_SZ)
#define OFF_W0 (OFF_XR + PROJ_SZ)      // 6 weights follow
#define SCRATCH_FLOATS (OFF_W0 + 6UL*W_SZ)

__device__ float g_scratch[SCRATCH_FLOATS];

#define STAGE_F 8192                   // floats per stage (A 4096 + B 4096)
#define SMEM_BYTES (3 * STAGE_F * 4)   // 98304

__device__ __forceinline__ uint32_t f2tf(float f) {
    uint32_t u;
    asm("cvt.rna.tf32.f32 %0, %1;" : "=r"(u) : "f"(f));
    return u;
}

__device__ __forceinline__ void mma8(float* c, const uint32_t* a, const uint32_t* b) {
    asm volatile(
        "mma.sync.aligned.m16n8k8.row.col.f32.tf32.tf32.f32 "
        "{%0,%1,%2,%3}, {%4,%5,%6,%7}, {%8,%9}, {%0,%1,%2,%3};"
        : "+f"(c[0]), "+f"(c[1]), "+f"(c[2]), "+f"(c[3])
        : "r"(a[0]), "r"(a[1]), "r"(a[2]), "r"(a[3]), "r"(b[0]), "r"(b[1]));
}

__device__ __forceinline__ void cpa16(uint32_t s, const void* g) {
    asm volatile("cp.async.cg.shared.global [%0], [%1], 16;" :: "r"(s), "l"(g));
}
#define CP_COMMIT asm volatile("cp.async.commit_group;")
#define CP_WAIT1  asm volatile("cp.async.wait_group 1;")

// ---------------------------------------------------------------------------
// C = alpha * A * op(B).  TRANSB=1: B[N,K] (NT).  TRANSB=0: B[K,N] (NN).
// 128x128x32 tiles, tf32 mma.sync, 3-stage cp.async ring, XOR-swizzled smem.
// Inputs MUST already be tf32-rounded bit patterns (pre-round pass/epilogues).
// ROUND_OUT: round outputs to tf32 (for tensors feeding later GEMMs).
// ---------------------------------------------------------------------------
template <int TRANSB, int ROUND_OUT>
__global__ void __launch_bounds__(256, 2) gemm_tf32(
    const float* __restrict__ A, size_t offA,
    const float* __restrict__ Bm, size_t offB,
    float* __restrict__ C, size_t offC,
    int K, int lda, int ldb, int ldc, float alpha,
    long long sAb, long long sAh, long long sBb, long long sBh,
    long long sCb, long long sCh)
{
    extern __shared__ float smem[];
    const float* Ap = A ? A : (const float*)(g_scratch + offA);
    const float* Bp = Bm ? Bm : (const float*)(g_scratch + offB);
    float*       Cp = C ? C : (g_scratch + offC);
    int zb = blockIdx.z / NH, zh = blockIdx.z % NH;
    Ap += (size_t)zb * sAb + (size_t)zh * sAh;
    Bp += (size_t)zb * sBb + (size_t)zh * sBh;
    Cp += (size_t)zb * sCb + (size_t)zh * sCh;

    uint32_t sbase;
    asm("{ .reg .u64 t; cvta.to.shared.u64 t, %1; cvt.u32.u64 %0, t; }"
        : "=r"(sbase) : "l"(smem));

    int tid  = threadIdx.x;
    int lane = tid & 31;
    int wid  = tid >> 5;
    int wm   = wid >> 2;         // 0..1
    int wn   = wid & 3;          // 0..3
    int la3  = lane & 3;
    int lq   = lane >> 2;        // 0..7

    // --- copy-thread coordinates ---
    int am  = tid >> 3;          // 0..31
    int ac8 = tid & 7;           // 16B-chunk in 128B row
    const float* aG0 = Ap + (size_t)(blockIdx.y * 128 + am) * lda + ac8 * 4;
    int aSw = (ac8 ^ (am & 7)) << 2;         // swizzled float offset in row

    const float* bG0;
    int bk = 0;
    if (TRANSB) {
        bG0 = Bp + (size_t)(blockIdx.x * 128 + am) * ldb + ac8 * 4;
    } else {
        bk  = tid >> 3;                       // 0..31 (k row)
        bG0 = Bp + (size_t)bk * ldb + blockIdx.x * 128;
    }

    auto issue = [&](int s, int kt) {
        uint32_t sa = sbase + (uint32_t)(s * STAGE_F) * 4;
#pragma unroll
        for (int i = 0; i < 4; i++)
            cpa16(sa + (uint32_t)((am + i * 32) * 32 + aSw) * 4,
                  aG0 + (size_t)kt * 32 + (size_t)i * 32 * lda);
        uint32_t sb = sa + 4096u * 4;
        if (TRANSB) {
#pragma unroll
            for (int i = 0; i < 4; i++)
                cpa16(sb + (uint32_t)((am + i * 32) * 32 + aSw) * 4,
                      bG0 + (size_t)kt * 32 + (size_t)i * 32 * ldb);
        } else {
#pragma unroll
            for (int i = 0; i < 4; i++) {
                int c32 = ac8 + i * 8;
                cpa16(sb + (uint32_t)(bk * 128 + (((c32) ^ ((bk & 3) << 1)) << 2)) * 4,
                      bG0 + (size_t)kt * 32 * ldb + (size_t)c32 * 4);
            }
        }
    };

    // --- fragment address constants ---
    int rm[4];
#pragma unroll
    for (int mt = 0; mt < 4; mt++) rm[mt] = (wm * 64 + mt * 16 + lq) * 32;
    int bnNT[4], bcNN[4];
#pragma unroll
    for (int nt = 0; nt < 4; nt++) {
        int n = wn * 32 + nt * 8 + lq;
        bnNT[nt] = n * 32;
        bcNN[nt] = (((n >> 2) ^ (la3 << 1)) << 2) + (n & 3);
    }

    float acc[4][4][4];
#pragma unroll
    for (int mt = 0; mt < 4; mt++)
#pragma unroll
        for (int nt = 0; nt < 4; nt++)
#pragma unroll
            for (int i = 0; i < 4; i++) acc[mt][nt][i] = 0.f;

    int nk = K >> 5;
    issue(0, 0); CP_COMMIT;
    issue(1, 1); CP_COMMIT;

    for (int kt = 0; kt < nk; ++kt) {
        CP_WAIT1;
        __syncthreads();
        if (kt + 2 < nk) issue((kt + 2) % 3, kt + 2);
        CP_COMMIT;

        const uint32_t* pa = (const uint32_t*)(smem + (kt % 3) * STAGE_F);
        const uint32_t* pb = pa + 4096;
#pragma unroll
        for (int ks = 0; ks < 4; ks++) {
            int swE = ((2 * ks) ^ lq) << 2;
            int swO = ((2 * ks + 1) ^ lq) << 2;
            uint32_t af[4][4], bf[4][2];
#pragma unroll
            for (int mt = 0; mt < 4; mt++) {
                af[mt][0] = pa[rm[mt] + swE + la3];
                af[mt][1] = pa[rm[mt] + 256 + swE + la3];
                af[mt][2] = pa[rm[mt] + swO + la3];
                af[mt][3] = pa[rm[mt] + 256 + swO + la3];
            }
#pragma unroll
            for (int nt = 0; nt < 4; nt++) {
                if (TRANSB) {
                    bf[nt][0] = pb[bnNT[nt] + swE + la3];
                    bf[nt][1] = pb[bnNT[nt] + swO + la3];
                } else {
                    bf[nt][0] = pb[(ks * 8 + la3) * 128 + bcNN[nt]];
                    bf[nt][1] = pb[(ks * 8 + la3 + 4) * 128 + bcNN[nt]];
                }
            }
#pragma unroll
            for (int mt = 0; mt < 4; mt++)
#pragma unroll
                for (int nt = 0; nt < 4; nt++)
                    mma8(acc[mt][nt], af[mt], bf[nt]);
        }
    }

    // epilogue
#pragma unroll
    for (int mt = 0; mt < 4; mt++) {
        int r = blockIdx.y * 128 + wm * 64 + mt * 16 + lq;
#pragma unroll
        for (int nt = 0; nt < 4; nt++) {
            int cc = blockIdx.x * 128 + wn * 32 + nt * 8 + (la3 << 1);
            float v[4];
#pragma unroll
            for (int i = 0; i < 4; i++) {
                v[i] = alpha * acc[mt][nt][i];
                if (ROUND_OUT) v[i] = __uint_as_float(f2tf(v[i]));
            }
            *(float2*)&Cp[(size_t)r * ldc + cc]       = make_float2(v[0], v[1]);
            *(float2*)&Cp[(size_t)(r + 8) * ldc + cc] = make_float2(v[2], v[3]);
        }
    }
}

// ---------------------------------------------------------------------------
// Pre-round external inputs to tf32 bit patterns in scratch.
// ---------------------------------------------------------------------------
__global__ void __launch_bounds__(256) round_copy(const float* __restrict__ src,
                                                  size_t dstOff, int n4)
{
    int i = blockIdx.x * 256 + threadIdx.x;
    if (i < n4) {
        float4 v = ((const float4*)src)[i];
        v.x = __uint_as_float(f2tf(v.x));
        v.y = __uint_as_float(f2tf(v.y));
        v.z = __uint_as_float(f2tf(v.z));
        v.w = __uint_as_float(f2tf(v.w));
        ((float4*)(g_scratch + dstOff))[i] = v;
    }
}

// ---------------------------------------------------------------------------
// P = softmax(S1_row) - lambda[h] * softmax(S2_row) -> S1 (tf32-rounded).
// ---------------------------------------------------------------------------
__global__ void __launch_bounds__(256) softmax_combine(const float* __restrict__ lam)
{
    int r = blockIdx.x;
    int h = (r / SSEQ) % NH;
    float lamh = lam[h];
    float* p1 = g_scratch + OFF_S1 + (size_t)r * SSEQ;
    float* p2 = g_scratch + OFF_S2 + (size_t)r * SSEQ;
    int t = threadIdx.x;

    float x1[8], x2[8];
#pragma unroll
    for (int i = 0; i < 8; i++) {
        x1[i] = p1[t + i * 256];
        x2[i] = p2[t + i * 256];
    }

    float m1 = -1e30f, m2 = -1e30f;
#pragma unroll
    for (int i = 0; i < 8; i++) {
        m1 = fmaxf(m1, x1[i]);
        m2 = fmaxf(m2, x2[i]);
    }
#pragma unroll
    for (int o = 16; o > 0; o >>= 1) {
        m1 = fmaxf(m1, __shfl_xor_sync(0xffffffffu, m1, o));
        m2 = fmaxf(m2, __shfl_xor_sync(0xffffffffu, m2, o));
    }
    __shared__ float sa[8], sb[8];
    int wid = t >> 5, lane = t & 31;
    if (lane == 0) { sa[wid] = m1; sb[wid] = m2; }
    __syncthreads();
    m1 = sa[0]; m2 = sb[0];
#pragma unroll
    for (int w = 1; w < 8; w++) {
        m1 = fmaxf(m1, sa[w]);
        m2 = fmaxf(m2, sb[w]);
    }
    __syncthreads();

    float e1 = 0.f, e2 = 0.f;
#pragma unroll
    for (int i = 0; i < 8; i++) {
        x1[i] = __expf(x1[i] - m1); e1 += x1[i];
        x2[i] = __expf(x2[i] - m2); e2 += x2[i];
    }
#pragma unroll
    for (int o = 16; o > 0; o >>= 1) {
        e1 += __shfl_xor_sync(0xffffffffu, e1, o);
        e2 += __shfl_xor_sync(0xffffffffu, e2, o);
    }
    if (lane == 0) { sa[wid] = e1; sb[wid] = e2; }
    __syncthreads();
    e1 = 0.f; e2 = 0.f;
#pragma unroll
    for (int w = 0; w < 8; w++) { e1 += sa[w]; e2 += sb[w]; }

    float i1 = 1.f / e1;
    float i2 = lamh / e2;
#pragma unroll
    for (int i = 0; i < 8; i++)
        p1[t + i * 256] = __uint_as_float(f2tf(x1[i] * i1 - x2[i] * i2));
}

// ---------------------------------------------------------------------------
extern "C" void kernel_launch(void* const* d_in, const int* in_sizes, int n_in,
                              void* d_out, int out_size)
{
    const float* x   = (const float*)d_in[0];
    const float* wq1 = (const float*)d_in[1];
    const float* wk1 = (const float*)d_in[2];
    const float* wq2 = (const float*)d_in[3];
    const float* wk2 = (const float*)d_in[4];
    const float* wv  = (const float*)d_in[5];
    const float* wo  = (const float*)d_in[6];
    const float* lam = (const float*)d_in[7];
    float* out = (float*)d_out;

    cudaFuncSetAttribute(gemm_tf32<1,1>, cudaFuncAttributeMaxDynamicSharedMemorySize, SMEM_BYTES);
    cudaFuncSetAttribute(gemm_tf32<1,0>, cudaFuncAttributeMaxDynamicSharedMemorySize, SMEM_BYTES);
    cudaFuncSetAttribute(gemm_tf32<0,1>, cudaFuncAttributeMaxDynamicSharedMemorySize, SMEM_BYTES);

    dim3 blk(256);

    // 0) pre-round inputs to tf32 bit patterns
    round_copy<<<(PROJ_SZ/4 + 255)/256, blk>>>(x, OFF_XR, PROJ_SZ/4);
    round_copy<<<(W_SZ/4 + 255)/256, blk>>>(wq1, OFF_W0 + 0*W_SZ, W_SZ/4);
    round_copy<<<(W_SZ/4 + 255)/256, blk>>>(wk1, OFF_W0 + 1*W_SZ, W_SZ/4);
    round_copy<<<(W_SZ/4 + 255)/256, blk>>>(wq2, OFF_W0 + 2*W_SZ, W_SZ/4);
    round_copy<<<(W_SZ/4 + 255)/256, blk>>>(wk2, OFF_W0 + 3*W_SZ, W_SZ/4);
    round_copy<<<(W_SZ/4 + 255)/256, blk>>>(wv,  OFF_W0 + 4*W_SZ, W_SZ/4);
    round_copy<<<(W_SZ/4 + 255)/256, blk>>>(wo,  OFF_W0 + 5*W_SZ, W_SZ/4);

    // 1) Projections (epilogue-rounded)
    dim3 gProj(16, 32, 1);
    gemm_tf32<1,1><<<gProj, blk, SMEM_BYTES>>>(nullptr, OFF_XR, nullptr, OFF_W0 + 0*W_SZ,
        nullptr, OFF_Q1, DM, DM, DM, DM, 1.f, 0,0,0,0,0,0);
    gemm_tf32<1,1><<<gProj, blk, SMEM_BYTES>>>(nullptr, OFF_XR, nullptr, OFF_W0 + 1*W_SZ,
        nullptr, OFF_K1, DM, DM, DM, DM, 1.f, 0,0,0,0,0,0);
    gemm_tf32<1,1><<<gProj, blk, SMEM_BYTES>>>(nullptr, OFF_XR, nullptr, OFF_W0 + 2*W_SZ,
        nullptr, OFF_Q2, DM, DM, DM, DM, 1.f, 0,0,0,0,0,0);
    gemm_tf32<1,1><<<gProj, blk, SMEM_BYTES>>>(nullptr, OFF_XR, nullptr, OFF_W0 + 3*W_SZ,
        nullptr, OFF_K2, DM, DM, DM, DM, 1.f, 0,0,0,0,0,0);
    gemm_tf32<1,1><<<gProj, blk, SMEM_BYTES>>>(nullptr, OFF_XR, nullptr, OFF_W0 + 4*W_SZ,
        nullptr, OFF_V,  DM, DM, DM, DM, 1.f, 0,0,0,0,0,0);

    // 2) Batched QK^T (scaled, un-rounded: feeds softmax)
    const float scl = 0.08838834764831845f;
    dim3 gQK(16, 16, BB * NH);
    long long sQb = (long long)SSEQ * DM, sQh = HD;
    long long sSb = (long long)NH * SSEQ * SSEQ, sSh = (long long)SSEQ * SSEQ;
    gemm_tf32<1,0><<<gQK, blk, SMEM_BYTES>>>(nullptr, OFF_Q1, nullptr, OFF_K1, nullptr, OFF_S1,
        HD, DM, DM, SSEQ, scl, sQb, sQh, sQb, sQh, sSb, sSh);
    gemm_tf32<1,0><<<gQK, blk, SMEM_BYTES>>>(nullptr, OFF_Q2, nullptr, OFF_K2, nullptr, OFF_S2,
        HD, DM, DM, SSEQ, scl, sQb, sQh, sQb, sQh, sSb, sSh);

    // 3) dual softmax + differential combine (tf32-rounded P into S1)
    softmax_combine<<<BB * NH * SSEQ, blk>>>(lam);

    // 4) Batched P @ V -> HO (epilogue-rounded)
    dim3 gPV(1, 16, BB * NH);
    gemm_tf32<0,1><<<gPV, blk, SMEM_BYTES>>>(nullptr, OFF_S1, nullptr, OFF_V, nullptr, OFF_HO,
        SSEQ, SSEQ, DM, DM, 1.f, sSb, sSh, sQb, sQh, sQb, sQh);

    // 5) Output projection -> d_out
    dim3 gOut(16, 32, 1);
    gemm_tf32<1,0><<<gOut, blk, SMEM_BYTES>>>(nullptr, OFF_HO, nullptr, OFF_W0 + 5*W_SZ,
        out, 0, DM, DM, DM, DM, 1.f, 0,0,0,0,0,0);
}

// round 6
// speedup vs baseline: 5.7034x; 1.4069x over previous
#include <cuda_runtime.h>
#include <cuda_fp16.h>
#include <math.h>
#include <stdint.h>

#define DM 2048
#define NH 16
#define HD 128
#define BB 2
#define SSEQ 2048

// half-element offsets in g_h
#define PROJ_SZ  (8388608UL)           // 4096*2048
#define W_SZ     (4194304UL)           // 2048*2048
#define SCORE_SZ (134217728UL)         // 2*16*2048*2048
#define OFF_XH (0UL)
#define OFF_WH (OFF_XH + PROJ_SZ)      // 6 weights
#define OFF_Q1 (OFF_WH + 6UL*W_SZ)
#define OFF_K1 (OFF_Q1 + PROJ_SZ)
#define OFF_Q2 (OFF_K1 + PROJ_SZ)
#define OFF_K2 (OFF_Q2 + PROJ_SZ)
#define OFF_VT (OFF_K2 + PROJ_SZ)      // V^T: [B, H, HD, S]
#define OFF_HO (OFF_VT + PROJ_SZ)
#define OFF_S1 (OFF_HO + PROJ_SZ)
#define OFF_S2 (OFF_S1 + SCORE_SZ)
#define TOTAL_H (OFF_S2 + SCORE_SZ)

__device__ __half g_h[TOTAL_H];

#define NSTG 3
#define STG_BYTES 32768u               // A 16KB + B 16KB (128 rows x 128B each)
#define HSMEM (NSTG * STG_BYTES)       // 98304

__device__ __forceinline__ uint32_t smem_u32(const void* p) {
    uint32_t a;
    asm("{ .reg .u64 t; cvta.to.shared.u64 t, %1; cvt.u32.u64 %0, t; }"
        : "=r"(a) : "l"(p));
    return a;
}
__device__ __forceinline__ void cpa16(uint32_t s, const void* g) {
    asm volatile("cp.async.cg.shared.global [%0], [%1], 16;" :: "r"(s), "l"(g));
}
#define CP_COMMIT asm volatile("cp.async.commit_group;")
#define CP_WAIT1  asm volatile("cp.async.wait_group 1;")

__device__ __forceinline__ void ldsm4(uint32_t* r, uint32_t addr) {
    asm volatile("ldmatrix.sync.aligned.m8n8.x4.shared.b16 {%0,%1,%2,%3}, [%4];"
        : "=r"(r[0]), "=r"(r[1]), "=r"(r[2]), "=r"(r[3]) : "r"(addr));
}
__device__ __forceinline__ void mma16(float* c, const uint32_t* a, const uint32_t* b) {
    asm volatile(
        "mma.sync.aligned.m16n8k16.row.col.f32.f16.f16.f32 "
        "{%0,%1,%2,%3}, {%4,%5,%6,%7}, {%8,%9}, {%0,%1,%2,%3};"
        : "+f"(c[0]), "+f"(c[1]), "+f"(c[2]), "+f"(c[3])
        : "r"(a[0]), "r"(a[1]), "r"(a[2]), "r"(a[3]), "r"(b[0]), "r"(b[1]));
}

// ===========================================================================
// fp16 NT GEMM: C[M,N] = alpha * A[M,K]h * B[N,K]h^T, fp32 accumulate.
// 128x128 CTA tile, BK=64, 3-stage cp.async ring, ldmatrix fragments.
// OUT_HALF: write C as half into g_h (else float to Cf).
// TRANS_OUT: scatter-write V^T layout [B,H,HD,S] (V projection only).
// ===========================================================================
template <int OUT_HALF, int TRANS_OUT>
__global__ void __launch_bounds__(256, 2) gemm_h(
    size_t offA, size_t offB, float* __restrict__ Cf, size_t offC,
    int K, int lda, int ldb, int ldc, float alpha,
    long long sAb, long long sAh, long long sBb, long long sBh,
    long long sCb, long long sCh)
{
    extern __shared__ __align__(1024) char dynsm[];
    const __half* Ap = g_h + offA;
    const __half* Bp = g_h + offB;
    int zb = blockIdx.z / NH, zh = blockIdx.z % NH;
    Ap += (size_t)zb * sAb + (size_t)zh * sAh;
    Bp += (size_t)zb * sBb + (size_t)zh * sBh;
    size_t cOff = (size_t)zb * sCb + (size_t)zh * sCh;

    uint32_t sbase = smem_u32(dynsm);
    int tid = threadIdx.x, lane = tid & 31, wid = tid >> 5;
    int wm = wid >> 2, wn = wid & 3;
    int la3 = lane & 3, lq = lane >> 2;

    // staging coords: row = tid>>1 (0..127), half-row h2 = tid&1 (4 chunks ea)
    int r = tid >> 1, h2 = tid & 1;
    const __half* aG = Ap + (size_t)(blockIdx.y * 128 + r) * lda + h2 * 32;
    const __half* bG = Bp + (size_t)(blockIdx.x * 128 + r) * ldb + h2 * 32;
    uint32_t swA[4];
#pragma unroll
    for (int i = 0; i < 4; i++)
        swA[i] = (uint32_t)(r * 128 + (((h2 * 4 + i) ^ (r & 7)) << 4));

    auto issue = [&](int s, int kt) {
        uint32_t st = sbase + (uint32_t)s * STG_BYTES;
        const __half* aP = aG + (size_t)kt * 64;
        const __half* bP = bG + (size_t)kt * 64;
#pragma unroll
        for (int i = 0; i < 4; i++) cpa16(st + swA[i], aP + i * 8);
#pragma unroll
        for (int i = 0; i < 4; i++) cpa16(st + 16384u + swA[i], bP + i * 8);
    };

    // ldmatrix per-lane coords
    int aRsel = lane & 15;               // row within 16
    int aHi   = lane >> 4;               // k-chunk half
    int bRsel = (lane & 7) | ((lane & 16) >> 1);
    int bHalf = (lane >> 3) & 1;
    uint32_t aRowB[4], bRowB[2];
#pragma unroll
    for (int mt = 0; mt < 4; mt++)
        aRowB[mt] = (uint32_t)((wm * 64 + mt * 16 + aRsel) * 128);
#pragma unroll
    for (int np = 0; np < 2; np++)
        bRowB[np] = (uint32_t)((wn * 32 + np * 16 + bRsel) * 128) + 16384u;
    int aXor = aRsel & 7, bXor = bRsel & 7;

    float acc[4][4][4];
#pragma unroll
    for (int mt = 0; mt < 4; mt++)
#pragma unroll
        for (int nt = 0; nt < 4; nt++)
#pragma unroll
            for (int i = 0; i < 4; i++) acc[mt][nt][i] = 0.f;

    int nk = K >> 6;
    issue(0, 0); CP_COMMIT;
    if (nk > 1) issue(1, 1);
    CP_COMMIT;

    for (int kt = 0; kt < nk; ++kt) {
        CP_WAIT1;
        __syncthreads();
        if (kt + 2 < nk) issue((kt + 2) % 3, kt + 2);
        CP_COMMIT;

        uint32_t st = sbase + (uint32_t)(kt % 3) * STG_BYTES;
#pragma unroll
        for (int ks = 0; ks < 4; ks++) {
            uint32_t aC = (uint32_t)(((2 * ks + aHi) ^ aXor) << 4);
            uint32_t bC = (uint32_t)(((2 * ks + bHalf) ^ bXor) << 4);
            uint32_t af[4][4], bf[2][4];
#pragma unroll
            for (int mt = 0; mt < 4; mt++) ldsm4(af[mt], st + aRowB[mt] + aC);
#pragma unroll
            for (int np = 0; np < 2; np++) ldsm4(bf[np], st + bRowB[np] + bC);
#pragma unroll
            for (int mt = 0; mt < 4; mt++)
#pragma unroll
                for (int nt = 0; nt < 4; nt++)
                    mma16(acc[mt][nt], af[mt], &bf[nt >> 1][(nt & 1) * 2]);
        }
        __syncthreads();
    }

    // epilogue
    if (TRANS_OUT) {
        __half* Ch = g_h + offC;
#pragma unroll
        for (int mt = 0; mt < 4; mt++) {
            int rr = blockIdx.y * 128 + wm * 64 + mt * 16 + lq;
#pragma unroll
            for (int nt = 0; nt < 4; nt++) {
                int cc = blockIdx.x * 128 + wn * 32 + nt * 8 + (la3 << 1);
#pragma unroll
                for (int e = 0; e < 4; e++) {
                    int tok = rr + ((e >> 1) << 3);      // +8 for e2,e3
                    int c   = cc + (e & 1);
                    int b = tok >> 11, t = tok & 2047;
                    int hh = c >> 7, dh = c & 127;
                    Ch[(((size_t)(b * NH + hh) * HD + dh) << 11) + t] =
                        __float2half_rn(alpha * acc[mt][nt][e]);
                }
            }
        }
    } else if (OUT_HALF) {
        __half* Ch = g_h + offC + cOff;
#pragma unroll
        for (int mt = 0; mt < 4; mt++) {
            int rr = blockIdx.y * 128 + wm * 64 + mt * 16 + lq;
#pragma unroll
            for (int nt = 0; nt < 4; nt++) {
                int cc = blockIdx.x * 128 + wn * 32 + nt * 8 + (la3 << 1);
                *(__half2*)&Ch[(size_t)rr * ldc + cc] =
                    __floats2half2_rn(alpha * acc[mt][nt][0], alpha * acc[mt][nt][1]);
                *(__half2*)&Ch[(size_t)(rr + 8) * ldc + cc] =
                    __floats2half2_rn(alpha * acc[mt][nt][2], alpha * acc[mt][nt][3]);
            }
        }
    } else {
        float* Cp = Cf + cOff;
#pragma unroll
        for (int mt = 0; mt < 4; mt++) {
            int rr = blockIdx.y * 128 + wm * 64 + mt * 16 + lq;
#pragma unroll
            for (int nt = 0; nt < 4; nt++) {
                int cc = blockIdx.x * 128 + wn * 32 + nt * 8 + (la3 << 1);
                *(float2*)&Cp[(size_t)rr * ldc + cc] =
                    make_float2(alpha * acc[mt][nt][0], alpha * acc[mt][nt][1]);
                *(float2*)&Cp[(size_t)(rr + 8) * ldc + cc] =
                    make_float2(alpha * acc[mt][nt][2], alpha * acc[mt][nt][3]);
            }
        }
    }
}

// ===========================================================================
// fp32 -> fp16 conversion into g_h
// ===========================================================================
__global__ void __launch_bounds__(256) f2h(const float* __restrict__ src,
                                           size_t dstOff, int n4)
{
    int i = blockIdx.x * 256 + threadIdx.x;
    if (i < n4) {
        float4 v = ((const float4*)src)[i];
        __half2* d = (__half2*)(g_h + dstOff);
        d[2 * i]     = __floats2half2_rn(v.x, v.y);
        d[2 * i + 1] = __floats2half2_rn(v.z, v.w);
    }
}

// ===========================================================================
// P = softmax(S1_row) - lambda[h]*softmax(S2_row) -> S1 (half)
// ===========================================================================
__global__ void __launch_bounds__(256) softmax_combine(const float* __restrict__ lam)
{
    int r = blockIdx.x;
    int h = (r / SSEQ) % NH;
    float lamh = lam[h];
    __half2* p1 = (__half2*)(g_h + OFF_S1) + (size_t)r * 1024;
    __half2* p2 = (__half2*)(g_h + OFF_S2) + (size_t)r * 1024;
    int t = threadIdx.x;

    float2 x1[4], x2[4];
#pragma unroll
    for (int i = 0; i < 4; i++) {
        x1[i] = __half22float2(p1[t + i * 256]);
        x2[i] = __half22float2(p2[t + i * 256]);
    }

    float m1 = -1e30f, m2 = -1e30f;
#pragma unroll
    for (int i = 0; i < 4; i++) {
        m1 = fmaxf(m1, fmaxf(x1[i].x, x1[i].y));
        m2 = fmaxf(m2, fmaxf(x2[i].x, x2[i].y));
    }
#pragma unroll
    for (int o = 16; o > 0; o >>= 1) {
        m1 = fmaxf(m1, __shfl_xor_sync(0xffffffffu, m1, o));
        m2 = fmaxf(m2, __shfl_xor_sync(0xffffffffu, m2, o));
    }
    __shared__ float sa[8], sb[8];
    int wid = t >> 5, lane = t & 31;
    if (lane == 0) { sa[wid] = m1; sb[wid] = m2; }
    __syncthreads();
    m1 = sa[0]; m2 = sb[0];
#pragma unroll
    for (int w = 1; w < 8; w++) { m1 = fmaxf(m1, sa[w]); m2 = fmaxf(m2, sb[w]); }
    __syncthreads();

    float e1 = 0.f, e2 = 0.f;
#pragma unroll
    for (int i = 0; i < 4; i++) {
        x1[i].x = __expf(x1[i].x - m1); x1[i].y = __expf(x1[i].y - m1);
        e1 += x1[i].x + x1[i].y;
        x2[i].x = __expf(x2[i].x - m2); x2[i].y = __expf(x2[i].y - m2);
        e2 += x2[i].x + x2[i].y;
    }
#pragma unroll
    for (int o = 16; o > 0; o >>= 1) {
        e1 += __shfl_xor_sync(0xffffffffu, e1, o);
        e2 += __shfl_xor_sync(0xffffffffu, e2, o);
    }
    if (lane == 0) { sa[wid] = e1; sb[wid] = e2; }
    __syncthreads();
    e1 = 0.f; e2 = 0.f;
#pragma unroll
    for (int w = 0; w < 8; w++) { e1 += sa[w]; e2 += sb[w]; }

    float i1 = 1.f / e1;
    float i2 = lamh / e2;
#pragma unroll
    for (int i = 0; i < 4; i++)
        p1[t + i * 256] = __floats2half2_rn(x1[i].x * i1 - x2[i].x * i2,
                                            x1[i].y * i1 - x2[i].y * i2);
}

// ===========================================================================
extern "C" void kernel_launch(void* const* d_in, const int* in_sizes, int n_in,
                              void* d_out, int out_size)
{
    const float* x   = (const float*)d_in[0];
    const float* wq1 = (const float*)d_in[1];
    const float* wk1 = (const float*)d_in[2];
    const float* wq2 = (const float*)d_in[3];
    const float* wk2 = (const float*)d_in[4];
    const float* wv  = (const float*)d_in[5];
    const float* wo  = (const float*)d_in[6];
    const float* lam = (const float*)d_in[7];
    float* out = (float*)d_out;

    cudaFuncSetAttribute(gemm_h<1,0>, cudaFuncAttributeMaxDynamicSharedMemorySize, HSMEM);
    cudaFuncSetAttribute(gemm_h<1,1>, cudaFuncAttributeMaxDynamicSharedMemorySize, HSMEM);
    cudaFuncSetAttribute(gemm_h<0,0>, cudaFuncAttributeMaxDynamicSharedMemorySize, HSMEM);

    dim3 blk(256);

    // 0) convert inputs to fp16
    f2h<<<(PROJ_SZ/4 + 255)/256, blk>>>(x, OFF_XH, PROJ_SZ/4);
    f2h<<<(W_SZ/4 + 255)/256, blk>>>(wq1, OFF_WH + 0*W_SZ, W_SZ/4);
    f2h<<<(W_SZ/4 + 255)/256, blk>>>(wk1, OFF_WH + 1*W_SZ, W_SZ/4);
    f2h<<<(W_SZ/4 + 255)/256, blk>>>(wq2, OFF_WH + 2*W_SZ, W_SZ/4);
    f2h<<<(W_SZ/4 + 255)/256, blk>>>(wk2, OFF_WH + 3*W_SZ, W_SZ/4);
    f2h<<<(W_SZ/4 + 255)/256, blk>>>(wv,  OFF_WH + 4*W_SZ, W_SZ/4);
    f2h<<<(W_SZ/4 + 255)/256, blk>>>(wo,  OFF_WH + 5*W_SZ, W_SZ/4);

    // 1) Projections (half outputs); V written transposed into VT
    dim3 gProj(16, 32, 1);
    gemm_h<1,0><<<gProj, blk, HSMEM>>>(OFF_XH, OFF_WH + 0*W_SZ, nullptr, OFF_Q1,
        DM, DM, DM, DM, 1.f, 0,0,0,0,0,0);
    gemm_h<1,0><<<gProj, blk, HSMEM>>>(OFF_XH, OFF_WH + 1*W_SZ, nullptr, OFF_K1,
        DM, DM, DM, DM, 1.f, 0,0,0,0,0,0);
    gemm_h<1,0><<<gProj, blk, HSMEM>>>(OFF_XH, OFF_WH + 2*W_SZ, nullptr, OFF_Q2,
        DM, DM, DM, DM, 1.f, 0,0,0,0,0,0);
    gemm_h<1,0><<<gProj, blk, HSMEM>>>(OFF_XH, OFF_WH + 3*W_SZ, nullptr, OFF_K2,
        DM, DM, DM, DM, 1.f, 0,0,0,0,0,0);
    gemm_h<1,1><<<gProj, blk, HSMEM>>>(OFF_XH, OFF_WH + 4*W_SZ, nullptr, OFF_VT,
        DM, DM, DM, DM, 1.f, 0,0,0,0,0,0);

    // 2) Batched QK^T (scaled) -> S1, S2 (half)
    const float scl = 0.08838834764831845f;
    dim3 gQK(16, 16, BB * NH);
    long long sQb = (long long)SSEQ * DM, sQh = HD;
    long long sSb = (long long)NH * SSEQ * SSEQ, sSh = (long long)SSEQ * SSEQ;
    gemm_h<1,0><<<gQK, blk, HSMEM>>>(OFF_Q1, OFF_K1, nullptr, OFF_S1,
        HD, DM, DM, SSEQ, scl, sQb, sQh, sQb, sQh, sSb, sSh);
    gemm_h<1,0><<<gQK, blk, HSMEM>>>(OFF_Q2, OFF_K2, nullptr, OFF_S2,
        HD, DM, DM, SSEQ, scl, sQb, sQh, sQb, sQh, sSb, sSh);

    // 3) dual softmax + differential combine -> P (half, in S1)
    softmax_combine<<<BB * NH * SSEQ, blk>>>(lam);

    // 4) Batched P @ V (NT vs V^T) -> HO (half)
    dim3 gPV(1, 16, BB * NH);
    long long sVb = (long long)NH * HD * SSEQ, sVh = (long long)HD * SSEQ;
    gemm_h<1,0><<<gPV, blk, HSMEM>>>(OFF_S1, OFF_VT, nullptr, OFF_HO,
        SSEQ, SSEQ, SSEQ, DM, 1.f, sSb, sSh, sVb, sVh, sQb, sQh);

    // 5) Output projection -> d_out (float)
    dim3 gOut(16, 32, 1);
    gemm_h<0,0><<<gOut, blk, HSMEM>>>(OFF_HO, OFF_WH + 5*W_SZ, out, 0,
        DM, DM, DM, DM, 1.f, 0,0,0,0,0,0);
}

// round 7
// speedup vs baseline: 6.2989x; 1.1044x over previous
#include <cuda_runtime.h>
#include <cuda_fp16.h>
#include <math.h>
#include <stdint.h>

#define DM 2048
#define NH 16
#define HD 128
#define BB 2
#define SSEQ 2048

// half-element offsets in g_h
#define PROJ_SZ  (8388608UL)           // 4096*2048
#define W_SZ     (4194304UL)           // 2048*2048
#define OFF_XH (0UL)
#define OFF_WH (OFF_XH + PROJ_SZ)      // 6 weights
#define OFF_Q1 (OFF_WH + 6UL*W_SZ)
#define OFF_K1 (OFF_Q1 + PROJ_SZ)
#define OFF_Q2 (OFF_K1 + PROJ_SZ)
#define OFF_K2 (OFF_Q2 + PROJ_SZ)
#define OFF_VT (OFF_K2 + PROJ_SZ)      // V^T: [B, H, HD, S]
#define OFF_HO (OFF_VT + PROJ_SZ)
#define TOTAL_H (OFF_HO + PROJ_SZ)

__device__ __half g_h[TOTAL_H];

__device__ __forceinline__ uint32_t smem_u32(const void* p) {
    uint32_t a;
    asm("{ .reg .u64 t; cvta.to.shared.u64 t, %1; cvt.u32.u64 %0, t; }"
        : "=r"(a) : "l"(p));
    return a;
}
__device__ __forceinline__ void cpa16(uint32_t s, const void* g) {
    asm volatile("cp.async.cg.shared.global [%0], [%1], 16;" :: "r"(s), "l"(g));
}
#define CP_COMMIT asm volatile("cp.async.commit_group;")
#define CP_WAIT1  asm volatile("cp.async.wait_group 1;")

__device__ __forceinline__ void ldsm4(uint32_t* r, uint32_t addr) {
    asm volatile("ldmatrix.sync.aligned.m8n8.x4.shared.b16 {%0,%1,%2,%3}, [%4];"
        : "=r"(r[0]), "=r"(r[1]), "=r"(r[2]), "=r"(r[3]) : "r"(addr));
}
__device__ __forceinline__ void mma16(float* c, const uint32_t* a, const uint32_t* b) {
    asm volatile(
        "mma.sync.aligned.m16n8k16.row.col.f32.f16.f16.f32 "
        "{%0,%1,%2,%3}, {%4,%5,%6,%7}, {%8,%9}, {%0,%1,%2,%3};"
        : "+f"(c[0]), "+f"(c[1]), "+f"(c[2]), "+f"(c[3])
        : "r"(a[0]), "r"(a[1]), "r"(a[2]), "r"(a[3]), "r"(b[0]), "r"(b[1]));
}

// ===========================================================================
// fp16 NT GEMM (projections + final output proj) — unchanged from round 6.
// ===========================================================================
#define NSTG 3
#define STG_BYTES 32768u
#define HSMEM (NSTG * STG_BYTES)

template <int OUT_HALF, int TRANS_OUT>
__global__ void __launch_bounds__(256, 2) gemm_h(
    size_t offA, size_t offB, float* __restrict__ Cf, size_t offC,
    int K, int lda, int ldb, int ldc, float alpha,
    long long sAb, long long sAh, long long sBb, long long sBh,
    long long sCb, long long sCh)
{
    extern __shared__ __align__(1024) char dynsm[];
    const __half* Ap = g_h + offA;
    const __half* Bp = g_h + offB;
    int zb = blockIdx.z / NH, zh = blockIdx.z % NH;
    Ap += (size_t)zb * sAb + (size_t)zh * sAh;
    Bp += (size_t)zb * sBb + (size_t)zh * sBh;
    size_t cOff = (size_t)zb * sCb + (size_t)zh * sCh;

    uint32_t sbase = smem_u32(dynsm);
    int tid = threadIdx.x, lane = tid & 31, wid = tid >> 5;
    int wm = wid >> 2, wn = wid & 3;
    int la3 = lane & 3, lq = lane >> 2;

    int r = tid >> 1, h2 = tid & 1;
    const __half* aG = Ap + (size_t)(blockIdx.y * 128 + r) * lda + h2 * 32;
    const __half* bG = Bp + (size_t)(blockIdx.x * 128 + r) * ldb + h2 * 32;
    uint32_t swA[4];
#pragma unroll
    for (int i = 0; i < 4; i++)
        swA[i] = (uint32_t)(r * 128 + (((h2 * 4 + i) ^ (r & 7)) << 4));

    auto issue = [&](int s, int kt) {
        uint32_t st = sbase + (uint32_t)s * STG_BYTES;
        const __half* aP = aG + (size_t)kt * 64;
        const __half* bP = bG + (size_t)kt * 64;
#pragma unroll
        for (int i = 0; i < 4; i++) cpa16(st + swA[i], aP + i * 8);
#pragma unroll
        for (int i = 0; i < 4; i++) cpa16(st + 16384u + swA[i], bP + i * 8);
    };

    int aRsel = lane & 15;
    int aHi   = lane >> 4;
    int bRsel = (lane & 7) | ((lane & 16) >> 1);
    int bHalf = (lane >> 3) & 1;
    uint32_t aRowB[4], bRowB[2];
#pragma unroll
    for (int mt = 0; mt < 4; mt++)
        aRowB[mt] = (uint32_t)((wm * 64 + mt * 16 + aRsel) * 128);
#pragma unroll
    for (int np = 0; np < 2; np++)
        bRowB[np] = (uint32_t)((wn * 32 + np * 16 + bRsel) * 128) + 16384u;
    int aXor = aRsel & 7, bXor = bRsel & 7;

    float acc[4][4][4];
#pragma unroll
    for (int mt = 0; mt < 4; mt++)
#pragma unroll
        for (int nt = 0; nt < 4; nt++)
#pragma unroll
            for (int i = 0; i < 4; i++) acc[mt][nt][i] = 0.f;

    int nk = K >> 6;
    issue(0, 0); CP_COMMIT;
    if (nk > 1) issue(1, 1);
    CP_COMMIT;

    for (int kt = 0; kt < nk; ++kt) {
        CP_WAIT1;
        __syncthreads();
        if (kt + 2 < nk) issue((kt + 2) % 3, kt + 2);
        CP_COMMIT;

        uint32_t st = sbase + (uint32_t)(kt % 3) * STG_BYTES;
#pragma unroll
        for (int ks = 0; ks < 4; ks++) {
            uint32_t aC = (uint32_t)(((2 * ks + aHi) ^ aXor) << 4);
            uint32_t bC = (uint32_t)(((2 * ks + bHalf) ^ bXor) << 4);
            uint32_t af[4][4], bf[2][4];
#pragma unroll
            for (int mt = 0; mt < 4; mt++) ldsm4(af[mt], st + aRowB[mt] + aC);
#pragma unroll
            for (int np = 0; np < 2; np++) ldsm4(bf[np], st + bRowB[np] + bC);
#pragma unroll
            for (int mt = 0; mt < 4; mt++)
#pragma unroll
                for (int nt = 0; nt < 4; nt++)
                    mma16(acc[mt][nt], af[mt], &bf[nt >> 1][(nt & 1) * 2]);
        }
        __syncthreads();
    }

    if (TRANS_OUT) {
        __half* Ch = g_h + offC;
#pragma unroll
        for (int mt = 0; mt < 4; mt++) {
            int rr = blockIdx.y * 128 + wm * 64 + mt * 16 + lq;
#pragma unroll
            for (int nt = 0; nt < 4; nt++) {
                int cc = blockIdx.x * 128 + wn * 32 + nt * 8 + (la3 << 1);
#pragma unroll
                for (int e = 0; e < 4; e++) {
                    int tok = rr + ((e >> 1) << 3);
                    int c   = cc + (e & 1);
                    int b = tok >> 11, t = tok & 2047;
                    int hh = c >> 7, dh = c & 127;
                    Ch[(((size_t)(b * NH + hh) * HD + dh) << 11) + t] =
                        __float2half_rn(alpha * acc[mt][nt][e]);
                }
            }
        }
    } else if (OUT_HALF) {
        __half* Ch = g_h + offC + cOff;
#pragma unroll
        for (int mt = 0; mt < 4; mt++) {
            int rr = blockIdx.y * 128 + wm * 64 + mt * 16 + lq;
#pragma unroll
            for (int nt = 0; nt < 4; nt++) {
                int cc = blockIdx.x * 128 + wn * 32 + nt * 8 + (la3 << 1);
                *(__half2*)&Ch[(size_t)rr * ldc + cc] =
                    __floats2half2_rn(alpha * acc[mt][nt][0], alpha * acc[mt][nt][1]);
                *(__half2*)&Ch[(size_t)(rr + 8) * ldc + cc] =
                    __floats2half2_rn(alpha * acc[mt][nt][2], alpha * acc[mt][nt][3]);
            }
        }
    } else {
        float* Cp = Cf + cOff;
#pragma unroll
        for (int mt = 0; mt < 4; mt++) {
            int rr = blockIdx.y * 128 + wm * 64 + mt * 16 + lq;
#pragma unroll
            for (int nt = 0; nt < 4; nt++) {
                int cc = blockIdx.x * 128 + wn * 32 + nt * 8 + (la3 << 1);
                *(float2*)&Cp[(size_t)rr * ldc + cc] =
                    make_float2(alpha * acc[mt][nt][0], alpha * acc[mt][nt][1]);
                *(float2*)&Cp[(size_t)(rr + 8) * ldc + cc] =
                    make_float2(alpha * acc[mt][nt][2], alpha * acc[mt][nt][3]);
            }
        }
    }
}

// ===========================================================================
// Fused differential flash attention.
// CTA: 64 q-rows, one (b,h). 8 warps: 0-3 branch1 (16 rows each), 4-7 branch2.
// KV tiles of 64; 3-stage cp.async ring {K1,K2,V^T} (48KB/stage).
// O = softmax(Q1K1^T)V - lam*softmax(Q2K2^T)V  via dual online softmax.
// Q1/Q2 pre-scaled by 1/sqrt(HD) (folded into projection alpha).
// ===========================================================================
#define QB 16384u
#define KVB 49152u
#define FL_SMEM (2u*QB + 3u*KVB)       // 180224

__global__ void __launch_bounds__(256, 1) flash_diff(const float* __restrict__ lam)
{
    extern __shared__ __align__(1024) char dynsm[];
    uint32_t sbase = smem_u32(dynsm);
    int qt = blockIdx.x;               // 0..31 (64-row q tile)
    int bh = blockIdx.y;               // 0..31
    int b = bh >> 4, h = bh & 15;
    int tid = threadIdx.x, lane = tid & 31, wid = tid >> 5;
    int br = wid >> 2;                 // branch 0/1
    int qr0 = (wid & 3) * 16;          // warp's q-row base within tile
    int la3 = lane & 3, lq = lane >> 2;
    int aRsel = lane & 15, aHi = lane >> 4;
    int bRsel = (lane & 7) | ((lane & 16) >> 1);
    int bHalf = (lane >> 3) & 1;

    const __half* q1g = g_h + OFF_Q1 + ((size_t)(b * SSEQ + qt * 64)) * DM + h * HD;
    const __half* q2g = g_h + OFF_Q2 + ((size_t)(b * SSEQ + qt * 64)) * DM + h * HD;
    const __half* k1g = g_h + OFF_K1 + ((size_t)(b * SSEQ)) * DM + h * HD;
    const __half* k2g = g_h + OFF_K2 + ((size_t)(b * SSEQ)) * DM + h * HD;
    const __half* vg  = g_h + OFF_VT + ((size_t)(b * NH + h) * HD) * SSEQ;

    // staging coords: Q/K tiles 64 rows x 128 halfs (two 64-half subtiles,
    // 128B rows each); V tile 128 rows x 64 halfs (128B rows).
    int r4 = tid >> 2, cg4 = tid & 3;
    int r2 = tid >> 1, cg2 = tid & 1;
    uint32_t qkOff[4], vOff[4];
#pragma unroll
    for (int i = 0; i < 4; i++) {
        int c = cg4 * 4 + i;           // 0..15
        qkOff[i] = (uint32_t)((c >> 3) * 8192 + r4 * 128 + (((c & 7) ^ (r4 & 7)) << 4));
        int cv = cg2 * 4 + i;          // 0..7
        vOff[i] = (uint32_t)(r2 * 128 + ((cv ^ (r2 & 7)) << 4));
    }

    auto issue_kv = [&](int s, int jj) {
        uint32_t st = sbase + 2u * QB + (uint32_t)s * KVB;
        const __half* k1p = k1g + (size_t)(jj * 64 + r4) * DM + cg4 * 32;
        const __half* k2p = k2g + (size_t)(jj * 64 + r4) * DM + cg4 * 32;
        const __half* vp  = vg + (size_t)r2 * SSEQ + jj * 64 + cg2 * 32;
#pragma unroll
        for (int i = 0; i < 4; i++) cpa16(st + qkOff[i], k1p + i * 8);
#pragma unroll
        for (int i = 0; i < 4; i++) cpa16(st + 16384u + qkOff[i], k2p + i * 8);
#pragma unroll
        for (int i = 0; i < 4; i++) cpa16(st + 32768u + vOff[i], vp + i * 8);
    };

    // prologue: Q1+Q2+stage0 (group0), stage1 (group1)
    {
        const __half* q1p = q1g + (size_t)r4 * DM + cg4 * 32;
        const __half* q2p = q2g + (size_t)r4 * DM + cg4 * 32;
#pragma unroll
        for (int i = 0; i < 4; i++) cpa16(sbase + qkOff[i], q1p + i * 8);
#pragma unroll
        for (int i = 0; i < 4; i++) cpa16(sbase + QB + qkOff[i], q2p + i * 8);
    }
    issue_kv(0, 0); CP_COMMIT;
    issue_kv(1, 1); CP_COMMIT;

    float O[16][4];
#pragma unroll
    for (int nt = 0; nt < 16; nt++)
#pragma unroll
        for (int i = 0; i < 4; i++) O[nt][i] = 0.f;
    float m0 = -1e30f, m1 = -1e30f, l0 = 0.f, l1 = 0.f;
    uint32_t qf[8][4];

    uint32_t sQ = sbase + (uint32_t)br * QB;
    int aXor = aRsel & 7, bXor = bRsel & 7;

    for (int jj = 0; jj < 32; ++jj) {
        CP_WAIT1;
        __syncthreads();
        if (jj == 0) {
            // load Q fragments (register-resident for whole kernel)
#pragma unroll
            for (int ks = 0; ks < 8; ks++) {
                int row = qr0 + aRsel;
                uint32_t addr = sQ + (uint32_t)((ks >> 2) * 8192 + row * 128 +
                    (((2 * (ks & 3) + aHi) ^ aXor) << 4));
                ldsm4(qf[ks], addr);
            }
        }
        if (jj + 2 < 32) issue_kv((jj + 2) % 3, jj + 2);
        CP_COMMIT;

        uint32_t stg = sbase + 2u * QB + (uint32_t)(jj % 3) * KVB;
        uint32_t sK = stg + (uint32_t)br * 16384u;

        // ---- S = Q Kb^T (16 rows x 64 cols per warp) ----
        float accS[8][4];
#pragma unroll
        for (int nt = 0; nt < 8; nt++)
#pragma unroll
            for (int i = 0; i < 4; i++) accS[nt][i] = 0.f;
#pragma unroll
        for (int ks = 0; ks < 8; ks++) {
            uint32_t bf[4][4];
#pragma unroll
            for (int np = 0; np < 4; np++) {
                int row = np * 16 + bRsel;
                ldsm4(bf[np], sK + (uint32_t)((ks >> 2) * 8192 + row * 128 +
                    (((2 * (ks & 3) + bHalf) ^ (row & 7)) << 4)));
            }
#pragma unroll
            for (int nt = 0; nt < 8; nt++)
                mma16(accS[nt], qf[ks], &bf[nt >> 1][(nt & 1) * 2]);
        }

        // ---- online softmax (rows lq and lq+8) ----
        float mx0 = -1e30f, mx1 = -1e30f;
#pragma unroll
        for (int nt = 0; nt < 8; nt++) {
            mx0 = fmaxf(mx0, fmaxf(accS[nt][0], accS[nt][1]));
            mx1 = fmaxf(mx1, fmaxf(accS[nt][2], accS[nt][3]));
        }
        mx0 = fmaxf(mx0, __shfl_xor_sync(0xffffffffu, mx0, 1));
        mx0 = fmaxf(mx0, __shfl_xor_sync(0xffffffffu, mx0, 2));
        mx1 = fmaxf(mx1, __shfl_xor_sync(0xffffffffu, mx1, 1));
        mx1 = fmaxf(mx1, __shfl_xor_sync(0xffffffffu, mx1, 2));
        float mn0 = fmaxf(m0, mx0), mn1 = fmaxf(m1, mx1);
        float sc0 = __expf(m0 - mn0), sc1 = __expf(m1 - mn1);
        m0 = mn0; m1 = mn1;
        l0 *= sc0; l1 *= sc1;

        uint32_t pf[4][4];
#pragma unroll
        for (int kt = 0; kt < 4; kt++) {
            float p00 = __expf(accS[2 * kt][0] - mn0);
            float p01 = __expf(accS[2 * kt][1] - mn0);
            float p10 = __expf(accS[2 * kt][2] - mn1);
            float p11 = __expf(accS[2 * kt][3] - mn1);
            float p20 = __expf(accS[2 * kt + 1][0] - mn0);
            float p21 = __expf(accS[2 * kt + 1][1] - mn0);
            float p30 = __expf(accS[2 * kt + 1][2] - mn1);
            float p31 = __expf(accS[2 * kt + 1][3] - mn1);
            l0 += p00 + p01 + p20 + p21;
            l1 += p10 + p11 + p30 + p31;
            __half2 h0 = __floats2half2_rn(p00, p01);
            __half2 h1 = __floats2half2_rn(p10, p11);
            __half2 h2 = __floats2half2_rn(p20, p21);
            __half2 h3 = __floats2half2_rn(p30, p31);
            pf[kt][0] = *(uint32_t*)&h0;
            pf[kt][1] = *(uint32_t*)&h1;
            pf[kt][2] = *(uint32_t*)&h2;
            pf[kt][3] = *(uint32_t*)&h3;
        }
#pragma unroll
        for (int nt = 0; nt < 16; nt++) {
            O[nt][0] *= sc0; O[nt][1] *= sc0;
            O[nt][2] *= sc1; O[nt][3] *= sc1;
        }

        // ---- O += P V (V^T tile: 128 dh rows x 64 seq cols) ----
        uint32_t sV = stg + 32768u;
#pragma unroll
        for (int ks = 0; ks < 4; ks++) {
            uint32_t vb[8][4];
#pragma unroll
            for (int np = 0; np < 8; np++) {
                int row = np * 16 + bRsel;
                ldsm4(vb[np], sV + (uint32_t)(row * 128 +
                    (((2 * ks + bHalf) ^ (row & 7)) << 4)));
            }
#pragma unroll
            for (int nt = 0; nt < 16; nt++)
                mma16(O[nt], pf[ks], &vb[nt >> 1][(nt & 1) * 2]);
        }
    }

    // ---- epilogue ----
    l0 += __shfl_xor_sync(0xffffffffu, l0, 1);
    l0 += __shfl_xor_sync(0xffffffffu, l0, 2);
    l1 += __shfl_xor_sync(0xffffffffu, l1, 1);
    l1 += __shfl_xor_sync(0xffffffffu, l1, 2);
    float inv0 = 1.f / l0, inv1 = 1.f / l1;

    float* sOut = (float*)(dynsm + 2u * QB);   // reuse stage area: 64 x 132 fp32
    __syncthreads();
    if (br == 1) {
        float lamh = lam[h];
#pragma unroll
        for (int nt = 0; nt < 16; nt++) {
            int col = nt * 8 + la3 * 2;
            *(float2*)&sOut[(qr0 + lq) * 132 + col] =
                make_float2(lamh * inv0 * O[nt][0], lamh * inv0 * O[nt][1]);
            *(float2*)&sOut[(qr0 + lq + 8) * 132 + col] =
                make_float2(lamh * inv1 * O[nt][2], lamh * inv1 * O[nt][3]);
        }
    }
    __syncthreads();
    if (br == 0) {
        __half* ho = g_h + OFF_HO + ((size_t)(b * SSEQ + qt * 64)) * DM + h * HD;
#pragma unroll
        for (int nt = 0; nt < 16; nt++) {
            int col = nt * 8 + la3 * 2;
            float2 s0 = *(float2*)&sOut[(qr0 + lq) * 132 + col];
            float2 s1 = *(float2*)&sOut[(qr0 + lq + 8) * 132 + col];
            *(__half2*)&ho[(size_t)(qr0 + lq) * DM + col] =
                __floats2half2_rn(O[nt][0] * inv0 - s0.x, O[nt][1] * inv0 - s0.y);
            *(__half2*)&ho[(size_t)(qr0 + lq + 8) * DM + col] =
                __floats2half2_rn(O[nt][2] * inv1 - s1.x, O[nt][3] * inv1 - s1.y);
        }
    }
}

// ===========================================================================
__global__ void __launch_bounds__(256) f2h(const float* __restrict__ src,
                                           size_t dstOff, int n4)
{
    int i = blockIdx.x * 256 + threadIdx.x;
    if (i < n4) {
        float4 v = ((const float4*)src)[i];
        __half2* d = (__half2*)(g_h + dstOff);
        d[2 * i]     = __floats2half2_rn(v.x, v.y);
        d[2 * i + 1] = __floats2half2_rn(v.z, v.w);
    }
}

// ===========================================================================
extern "C" void kernel_launch(void* const* d_in, const int* in_sizes, int n_in,
                              void* d_out, int out_size)
{
    const float* x   = (const float*)d_in[0];
    const float* wq1 = (const float*)d_in[1];
    const float* wk1 = (const float*)d_in[2];
    const float* wq2 = (const float*)d_in[3];
    const float* wk2 = (const float*)d_in[4];
    const float* wv  = (const float*)d_in[5];
    const float* wo  = (const float*)d_in[6];
    const float* lam = (const float*)d_in[7];
    float* out = (float*)d_out;

    cudaFuncSetAttribute(gemm_h<1,0>, cudaFuncAttributeMaxDynamicSharedMemorySize, HSMEM);
    cudaFuncSetAttribute(gemm_h<1,1>, cudaFuncAttributeMaxDynamicSharedMemorySize, HSMEM);
    cudaFuncSetAttribute(gemm_h<0,0>, cudaFuncAttributeMaxDynamicSharedMemorySize, HSMEM);
    cudaFuncSetAttribute(flash_diff, cudaFuncAttributeMaxDynamicSharedMemorySize, FL_SMEM);

    dim3 blk(256);

    // 0) convert inputs to fp16
    f2h<<<(PROJ_SZ/4 + 255)/256, blk>>>(x, OFF_XH, PROJ_SZ/4);
    f2h<<<(W_SZ/4 + 255)/256, blk>>>(wq1, OFF_WH + 0*W_SZ, W_SZ/4);
    f2h<<<(W_SZ/4 + 255)/256, blk>>>(wk1, OFF_WH + 1*W_SZ, W_SZ/4);
    f2h<<<(W_SZ/4 + 255)/256, blk>>>(wq2, OFF_WH + 2*W_SZ, W_SZ/4);
    f2h<<<(W_SZ/4 + 255)/256, blk>>>(wk2, OFF_WH + 3*W_SZ, W_SZ/4);
    f2h<<<(W_SZ/4 + 255)/256, blk>>>(wv,  OFF_WH + 4*W_SZ, W_SZ/4);
    f2h<<<(W_SZ/4 + 255)/256, blk>>>(wo,  OFF_WH + 5*W_SZ, W_SZ/4);

    // 1) Projections; Q1/Q2 pre-scaled by 1/sqrt(HD); V written transposed
    const float scl = 0.08838834764831845f;
    dim3 gProj(16, 32, 1);
    gemm_h<1,0><<<gProj, blk, HSMEM>>>(OFF_XH, OFF_WH + 0*W_SZ, nullptr, OFF_Q1,
        DM, DM, DM, DM, scl, 0,0,0,0,0,0);
    gemm_h<1,0><<<gProj, blk, HSMEM>>>(OFF_XH, OFF_WH + 1*W_SZ, nullptr, OFF_K1,
        DM, DM, DM, DM, 1.f, 0,0,0,0,0,0);
    gemm_h<1,0><<<gProj, blk, HSMEM>>>(OFF_XH, OFF_WH + 2*W_SZ, nullptr, OFF_Q2,
        DM, DM, DM, DM, scl, 0,0,0,0,0,0);
    gemm_h<1,0><<<gProj, blk, HSMEM>>>(OFF_XH, OFF_WH + 3*W_SZ, nullptr, OFF_K2,
        DM, DM, DM, DM, 1.f, 0,0,0,0,0,0);
    gemm_h<1,1><<<gProj, blk, HSMEM>>>(OFF_XH, OFF_WH + 4*W_SZ, nullptr, OFF_VT,
        DM, DM, DM, DM, 1.f, 0,0,0,0,0,0);

    // 2) Fused differential flash attention -> HO (half)
    dim3 gFl(SSEQ / 64, BB * NH);
    flash_diff<<<gFl, blk, FL_SMEM>>>(lam);

    // 3) Output projection -> d_out (float)
    dim3 gOut(16, 32, 1);
    gemm_h<0,0><<<gOut, blk, HSMEM>>>(OFF_HO, OFF_WH + 5*W_SZ, out, 0,
        DM, DM, DM, DM, 1.f, 0,0,0,0,0,0);
}

// round 8
// speedup vs baseline: 7.1062x; 1.1282x over previous
#include <cuda_runtime.h>
#include <cuda_fp16.h>
#include <math.h>
#include <stdint.h>

#define DM 2048
#define NH 16
#define HD 128
#define BB 2
#define SSEQ 2048

// half-element offsets in g_h
#define PROJ_SZ  (8388608UL)           // 4096*2048
#define W_SZ     (4194304UL)           // 2048*2048
#define OFF_XH (0UL)
#define OFF_WH (OFF_XH + PROJ_SZ)      // 6 weights (contiguous after x)
#define OFF_Q1 (OFF_WH + 6UL*W_SZ)
#define OFF_K1 (OFF_Q1 + PROJ_SZ)
#define OFF_Q2 (OFF_K1 + PROJ_SZ)
#define OFF_K2 (OFF_Q2 + PROJ_SZ)
#define OFF_VT (OFF_K2 + PROJ_SZ)      // V^T: [B, H, HD, S]
#define OFF_HO (OFF_VT + PROJ_SZ)
#define TOTAL_H (OFF_HO + PROJ_SZ)

#define SCL 0.08838834764831845f       // 1/sqrt(128)

__device__ __half g_h[TOTAL_H];

__device__ __forceinline__ uint32_t smem_u32(const void* p) {
    uint32_t a;
    asm("{ .reg .u64 t; cvta.to.shared.u64 t, %1; cvt.u32.u64 %0, t; }"
        : "=r"(a) : "l"(p));
    return a;
}
__device__ __forceinline__ void cpa16(uint32_t s, const void* g) {
    asm volatile("cp.async.cg.shared.global [%0], [%1], 16;" :: "r"(s), "l"(g));
}
#define CP_COMMIT asm volatile("cp.async.commit_group;")
#define CP_WAIT1  asm volatile("cp.async.wait_group 1;")

__device__ __forceinline__ void ldsm4(uint32_t* r, uint32_t addr) {
    asm volatile("ldmatrix.sync.aligned.m8n8.x4.shared.b16 {%0,%1,%2,%3}, [%4];"
        : "=r"(r[0]), "=r"(r[1]), "=r"(r[2]), "=r"(r[3]) : "r"(addr));
}
__device__ __forceinline__ void mma16(float* c, const uint32_t* a, const uint32_t* b) {
    asm volatile(
        "mma.sync.aligned.m16n8k16.row.col.f32.f16.f16.f32 "
        "{%0,%1,%2,%3}, {%4,%5,%6,%7}, {%8,%9}, {%0,%1,%2,%3};"
        : "+f"(c[0]), "+f"(c[1]), "+f"(c[2]), "+f"(c[3])
        : "r"(a[0]), "r"(a[1]), "r"(a[2]), "r"(a[3]), "r"(b[0]), "r"(b[1]));
}

#define NSTG 3
#define STG_BYTES 32768u
#define HSMEM (NSTG * STG_BYTES)

// ===========================================================================
// Combined projection GEMM: z = weight index (0..4).
// C_z[4096,2048] = alpha_z * X * W_z^T; z==4 writes V transposed.
// ===========================================================================
__global__ void __launch_bounds__(256, 2) gemm_proj()
{
    extern __shared__ __align__(1024) char dynsm[];
    int z = blockIdx.z;
    const __half* Ap = g_h + OFF_XH;
    const __half* Bp = g_h + OFF_WH + (size_t)z * W_SZ;
    float alpha = (z == 0 || z == 2) ? SCL : 1.f;

    uint32_t sbase = smem_u32(dynsm);
    int tid = threadIdx.x, lane = tid & 31, wid = tid >> 5;
    int wm = wid >> 2, wn = wid & 3;
    int la3 = lane & 3, lq = lane >> 2;

    int r = tid >> 1, h2 = tid & 1;
    const __half* aG = Ap + (size_t)(blockIdx.y * 128 + r) * DM + h2 * 32;
    const __half* bG = Bp + (size_t)(blockIdx.x * 128 + r) * DM + h2 * 32;
    uint32_t swA[4];
#pragma unroll
    for (int i = 0; i < 4; i++)
        swA[i] = (uint32_t)(r * 128 + (((h2 * 4 + i) ^ (r & 7)) << 4));

    auto issue = [&](int s, int kt) {
        uint32_t st = sbase + (uint32_t)s * STG_BYTES;
        const __half* aP = aG + (size_t)kt * 64;
        const __half* bP = bG + (size_t)kt * 64;
#pragma unroll
        for (int i = 0; i < 4; i++) cpa16(st + swA[i], aP + i * 8);
#pragma unroll
        for (int i = 0; i < 4; i++) cpa16(st + 16384u + swA[i], bP + i * 8);
    };

    int aRsel = lane & 15, aHi = lane >> 4;
    int bRsel = (lane & 7) | ((lane & 16) >> 1);
    int bHalf = (lane >> 3) & 1;
    uint32_t aRowB[4], bRowB[2];
#pragma unroll
    for (int mt = 0; mt < 4; mt++)
        aRowB[mt] = (uint32_t)((wm * 64 + mt * 16 + aRsel) * 128);
#pragma unroll
    for (int np = 0; np < 2; np++)
        bRowB[np] = (uint32_t)((wn * 32 + np * 16 + bRsel) * 128) + 16384u;
    int aXor = aRsel & 7, bXor = bRsel & 7;

    float acc[4][4][4];
#pragma unroll
    for (int mt = 0; mt < 4; mt++)
#pragma unroll
        for (int nt = 0; nt < 4; nt++)
#pragma unroll
            for (int i = 0; i < 4; i++) acc[mt][nt][i] = 0.f;

    issue(0, 0); CP_COMMIT;
    issue(1, 1); CP_COMMIT;

#pragma unroll 1
    for (int kt = 0; kt < 32; ++kt) {
        CP_WAIT1;
        __syncthreads();
        if (kt + 2 < 32) issue((kt + 2) % 3, kt + 2);
        CP_COMMIT;

        uint32_t st = sbase + (uint32_t)(kt % 3) * STG_BYTES;
#pragma unroll
        for (int ks = 0; ks < 4; ks++) {
            uint32_t aC = (uint32_t)(((2 * ks + aHi) ^ aXor) << 4);
            uint32_t bC = (uint32_t)(((2 * ks + bHalf) ^ bXor) << 4);
            uint32_t af[4][4], bf[2][4];
#pragma unroll
            for (int mt = 0; mt < 4; mt++) ldsm4(af[mt], st + aRowB[mt] + aC);
#pragma unroll
            for (int np = 0; np < 2; np++) ldsm4(bf[np], st + bRowB[np] + bC);
#pragma unroll
            for (int mt = 0; mt < 4; mt++)
#pragma unroll
                for (int nt = 0; nt < 4; nt++)
                    mma16(acc[mt][nt], af[mt], &bf[nt >> 1][(nt & 1) * 2]);
        }
    }

    if (z == 4) {
        // V: write transposed into VT [B,H,HD,S]
        __half* Ch = g_h + OFF_VT;
#pragma unroll
        for (int mt = 0; mt < 4; mt++) {
            int rr = blockIdx.y * 128 + wm * 64 + mt * 16 + lq;
#pragma unroll
            for (int nt = 0; nt < 4; nt++) {
                int cc = blockIdx.x * 128 + wn * 32 + nt * 8 + (la3 << 1);
#pragma unroll
                for (int e = 0; e < 4; e++) {
                    int tok = rr + ((e >> 1) << 3);
                    int c   = cc + (e & 1);
                    int bb = tok >> 11, t = tok & 2047;
                    int hh = c >> 7, dh = c & 127;
                    Ch[(((size_t)(bb * NH + hh) * HD + dh) << 11) + t] =
                        __float2half_rn(acc[mt][nt][e]);
                }
            }
        }
    } else {
        __half* Ch = g_h + OFF_Q1 + (size_t)z * PROJ_SZ;
#pragma unroll
        for (int mt = 0; mt < 4; mt++) {
            int rr = blockIdx.y * 128 + wm * 64 + mt * 16 + lq;
#pragma unroll
            for (int nt = 0; nt < 4; nt++) {
                int cc = blockIdx.x * 128 + wn * 32 + nt * 8 + (la3 << 1);
                *(__half2*)&Ch[(size_t)rr * DM + cc] =
                    __floats2half2_rn(alpha * acc[mt][nt][0], alpha * acc[mt][nt][1]);
                *(__half2*)&Ch[(size_t)(rr + 8) * DM + cc] =
                    __floats2half2_rn(alpha * acc[mt][nt][2], alpha * acc[mt][nt][3]);
            }
        }
    }
}

// ===========================================================================
// Output projection: out[4096,2048] = HO * Wo^T (float out)
// ===========================================================================
__global__ void __launch_bounds__(256, 2) gemm_out(float* __restrict__ Cf)
{
    extern __shared__ __align__(1024) char dynsm[];
    const __half* Ap = g_h + OFF_HO;
    const __half* Bp = g_h + OFF_WH + 5UL * W_SZ;

    uint32_t sbase = smem_u32(dynsm);
    int tid = threadIdx.x, lane = tid & 31, wid = tid >> 5;
    int wm = wid >> 2, wn = wid & 3;
    int la3 = lane & 3, lq = lane >> 2;

    int r = tid >> 1, h2 = tid & 1;
    const __half* aG = Ap + (size_t)(blockIdx.y * 128 + r) * DM + h2 * 32;
    const __half* bG = Bp + (size_t)(blockIdx.x * 128 + r) * DM + h2 * 32;
    uint32_t swA[4];
#pragma unroll
    for (int i = 0; i < 4; i++)
        swA[i] = (uint32_t)(r * 128 + (((h2 * 4 + i) ^ (r & 7)) << 4));

    auto issue = [&](int s, int kt) {
        uint32_t st = sbase + (uint32_t)s * STG_BYTES;
        const __half* aP = aG + (size_t)kt * 64;
        const __half* bP = bG + (size_t)kt * 64;
#pragma unroll
        for (int i = 0; i < 4; i++) cpa16(st + swA[i], aP + i * 8);
#pragma unroll
        for (int i = 0; i < 4; i++) cpa16(st + 16384u + swA[i], bP + i * 8);
    };

    int aRsel = lane & 15, aHi = lane >> 4;
    int bRsel = (lane & 7) | ((lane & 16) >> 1);
    int bHalf = (lane >> 3) & 1;
    uint32_t aRowB[4], bRowB[2];
#pragma unroll
    for (int mt = 0; mt < 4; mt++)
        aRowB[mt] = (uint32_t)((wm * 64 + mt * 16 + aRsel) * 128);
#pragma unroll
    for (int np = 0; np < 2; np++)
        bRowB[np] = (uint32_t)((wn * 32 + np * 16 + bRsel) * 128) + 16384u;
    int aXor = aRsel & 7, bXor = bRsel & 7;

    float acc[4][4][4];
#pragma unroll
    for (int mt = 0; mt < 4; mt++)
#pragma unroll
        for (int nt = 0; nt < 4; nt++)
#pragma unroll
            for (int i = 0; i < 4; i++) acc[mt][nt][i] = 0.f;

    issue(0, 0); CP_COMMIT;
    issue(1, 1); CP_COMMIT;

#pragma unroll 1
    for (int kt = 0; kt < 32; ++kt) {
        CP_WAIT1;
        __syncthreads();
        if (kt + 2 < 32) issue((kt + 2) % 3, kt + 2);
        CP_COMMIT;

        uint32_t st = sbase + (uint32_t)(kt % 3) * STG_BYTES;
#pragma unroll
        for (int ks = 0; ks < 4; ks++) {
            uint32_t aC = (uint32_t)(((2 * ks + aHi) ^ aXor) << 4);
            uint32_t bC = (uint32_t)(((2 * ks + bHalf) ^ bXor) << 4);
            uint32_t af[4][4], bf[2][4];
#pragma unroll
            for (int mt = 0; mt < 4; mt++) ldsm4(af[mt], st + aRowB[mt] + aC);
#pragma unroll
            for (int np = 0; np < 2; np++) ldsm4(bf[np], st + bRowB[np] + bC);
#pragma unroll
            for (int mt = 0; mt < 4; mt++)
#pragma unroll
                for (int nt = 0; nt < 4; nt++)
                    mma16(acc[mt][nt], af[mt], &bf[nt >> 1][(nt & 1) * 2]);
        }
    }

#pragma unroll
    for (int mt = 0; mt < 4; mt++) {
        int rr = blockIdx.y * 128 + wm * 64 + mt * 16 + lq;
#pragma unroll
        for (int nt = 0; nt < 4; nt++) {
            int cc = blockIdx.x * 128 + wn * 32 + nt * 8 + (la3 << 1);
            *(float2*)&Cf[(size_t)rr * DM + cc] =
                make_float2(acc[mt][nt][0], acc[mt][nt][1]);
            *(float2*)&Cf[(size_t)(rr + 8) * DM + cc] =
                make_float2(acc[mt][nt][2], acc[mt][nt][3]);
        }
    }
}

// ===========================================================================
// Fused differential flash attention (unchanged from round 7).
// ===========================================================================
#define QB 16384u
#define KVB 49152u
#define FL_SMEM (2u*QB + 3u*KVB)

__global__ void __launch_bounds__(256, 1) flash_diff(const float* __restrict__ lam)
{
    extern __shared__ __align__(1024) char dynsm[];
    uint32_t sbase = smem_u32(dynsm);
    int qt = blockIdx.x;
    int bh = blockIdx.y;
    int b = bh >> 4, h = bh & 15;
    int tid = threadIdx.x, lane = tid & 31, wid = tid >> 5;
    int br = wid >> 2;
    int qr0 = (wid & 3) * 16;
    int la3 = lane & 3, lq = lane >> 2;
    int aRsel = lane & 15, aHi = lane >> 4;
    int bRsel = (lane & 7) | ((lane & 16) >> 1);
    int bHalf = (lane >> 3) & 1;

    const __half* q1g = g_h + OFF_Q1 + ((size_t)(b * SSEQ + qt * 64)) * DM + h * HD;
    const __half* q2g = g_h + OFF_Q2 + ((size_t)(b * SSEQ + qt * 64)) * DM + h * HD;
    const __half* k1g = g_h + OFF_K1 + ((size_t)(b * SSEQ)) * DM + h * HD;
    const __half* k2g = g_h + OFF_K2 + ((size_t)(b * SSEQ)) * DM + h * HD;
    const __half* vg  = g_h + OFF_VT + ((size_t)(b * NH + h) * HD) * SSEQ;

    int r4 = tid >> 2, cg4 = tid & 3;
    int r2 = tid >> 1, cg2 = tid & 1;
    uint32_t qkOff[4], vOff[4];
#pragma unroll
    for (int i = 0; i < 4; i++) {
        int c = cg4 * 4 + i;
        qkOff[i] = (uint32_t)((c >> 3) * 8192 + r4 * 128 + (((c & 7) ^ (r4 & 7)) << 4));
        int cv = cg2 * 4 + i;
        vOff[i] = (uint32_t)(r2 * 128 + ((cv ^ (r2 & 7)) << 4));
    }

    auto issue_kv = [&](int s, int jj) {
        uint32_t st = sbase + 2u * QB + (uint32_t)s * KVB;
        const __half* k1p = k1g + (size_t)(jj * 64 + r4) * DM + cg4 * 32;
        const __half* k2p = k2g + (size_t)(jj * 64 + r4) * DM + cg4 * 32;
        const __half* vp  = vg + (size_t)r2 * SSEQ + jj * 64 + cg2 * 32;
#pragma unroll
        for (int i = 0; i < 4; i++) cpa16(st + qkOff[i], k1p + i * 8);
#pragma unroll
        for (int i = 0; i < 4; i++) cpa16(st + 16384u + qkOff[i], k2p + i * 8);
#pragma unroll
        for (int i = 0; i < 4; i++) cpa16(st + 32768u + vOff[i], vp + i * 8);
    };

    {
        const __half* q1p = q1g + (size_t)r4 * DM + cg4 * 32;
        const __half* q2p = q2g + (size_t)r4 * DM + cg4 * 32;
#pragma unroll
        for (int i = 0; i < 4; i++) cpa16(sbase + qkOff[i], q1p + i * 8);
#pragma unroll
        for (int i = 0; i < 4; i++) cpa16(sbase + QB + qkOff[i], q2p + i * 8);
    }
    issue_kv(0, 0); CP_COMMIT;
    issue_kv(1, 1); CP_COMMIT;

    float O[16][4];
#pragma unroll
    for (int nt = 0; nt < 16; nt++)
#pragma unroll
        for (int i = 0; i < 4; i++) O[nt][i] = 0.f;
    float m0 = -1e30f, m1 = -1e30f, l0 = 0.f, l1 = 0.f;
    uint32_t qf[8][4];

    uint32_t sQ = sbase + (uint32_t)br * QB;
    int aXor = aRsel & 7;

    for (int jj = 0; jj < 32; ++jj) {
        CP_WAIT1;
        __syncthreads();
        if (jj == 0) {
#pragma unroll
            for (int ks = 0; ks < 8; ks++) {
                int row = qr0 + aRsel;
                uint32_t addr = sQ + (uint32_t)((ks >> 2) * 8192 + row * 128 +
                    (((2 * (ks & 3) + aHi) ^ aXor) << 4));
                ldsm4(qf[ks], addr);
            }
        }
        if (jj + 2 < 32) issue_kv((jj + 2) % 3, jj + 2);
        CP_COMMIT;

        uint32_t stg = sbase + 2u * QB + (uint32_t)(jj % 3) * KVB;
        uint32_t sK = stg + (uint32_t)br * 16384u;

        float accS[8][4];
#pragma unroll
        for (int nt = 0; nt < 8; nt++)
#pragma unroll
            for (int i = 0; i < 4; i++) accS[nt][i] = 0.f;
#pragma unroll
        for (int ks = 0; ks < 8; ks++) {
            uint32_t bf[4][4];
#pragma unroll
            for (int np = 0; np < 4; np++) {
                int row = np * 16 + bRsel;
                ldsm4(bf[np], sK + (uint32_t)((ks >> 2) * 8192 + row * 128 +
                    (((2 * (ks & 3) + bHalf) ^ (row & 7)) << 4)));
            }
#pragma unroll
            for (int nt = 0; nt < 8; nt++)
                mma16(accS[nt], qf[ks], &bf[nt >> 1][(nt & 1) * 2]);
        }

        float mx0 = -1e30f, mx1 = -1e30f;
#pragma unroll
        for (int nt = 0; nt < 8; nt++) {
            mx0 = fmaxf(mx0, fmaxf(accS[nt][0], accS[nt][1]));
            mx1 = fmaxf(mx1, fmaxf(accS[nt][2], accS[nt][3]));
        }
        mx0 = fmaxf(mx0, __shfl_xor_sync(0xffffffffu, mx0, 1));
        mx0 = fmaxf(mx0, __shfl_xor_sync(0xffffffffu, mx0, 2));
        mx1 = fmaxf(mx1, __shfl_xor_sync(0xffffffffu, mx1, 1));
        mx1 = fmaxf(mx1, __shfl_xor_sync(0xffffffffu, mx1, 2));
        float mn0 = fmaxf(m0, mx0), mn1 = fmaxf(m1, mx1);
        float sc0 = __expf(m0 - mn0), sc1 = __expf(m1 - mn1);
        m0 = mn0; m1 = mn1;
        l0 *= sc0; l1 *= sc1;

        uint32_t pf[4][4];
#pragma unroll
        for (int kt = 0; kt < 4; kt++) {
            float p00 = __expf(accS[2 * kt][0] - mn0);
            float p01 = __expf(accS[2 * kt][1] - mn0);
            float p10 = __expf(accS[2 * kt][2] - mn1);
            float p11 = __expf(accS[2 * kt][3] - mn1);
            float p20 = __expf(accS[2 * kt + 1][0] - mn0);
            float p21 = __expf(accS[2 * kt + 1][1] - mn0);
            float p30 = __expf(accS[2 * kt + 1][2] - mn1);
            float p31 = __expf(accS[2 * kt + 1][3] - mn1);
            l0 += p00 + p01 + p20 + p21;
            l1 += p10 + p11 + p30 + p31;
            __half2 h0 = __floats2half2_rn(p00, p01);
            __half2 h1 = __floats2half2_rn(p10, p11);
            __half2 h2 = __floats2half2_rn(p20, p21);
            __half2 h3 = __floats2half2_rn(p30, p31);
            pf[kt][0] = *(uint32_t*)&h0;
            pf[kt][1] = *(uint32_t*)&h1;
            pf[kt][2] = *(uint32_t*)&h2;
            pf[kt][3] = *(uint32_t*)&h3;
        }
#pragma unroll
        for (int nt = 0; nt < 16; nt++) {
            O[nt][0] *= sc0; O[nt][1] *= sc0;
            O[nt][2] *= sc1; O[nt][3] *= sc1;
        }

        uint32_t sV = stg + 32768u;
#pragma unroll
        for (int ks = 0; ks < 4; ks++) {
            uint32_t vb[8][4];
#pragma unroll
            for (int np = 0; np < 8; np++) {
                int row = np * 16 + bRsel;
                ldsm4(vb[np], sV + (uint32_t)(row * 128 +
                    (((2 * ks + bHalf) ^ (row & 7)) << 4)));
            }
#pragma unroll
            for (int nt = 0; nt < 16; nt++)
                mma16(O[nt], pf[ks], &vb[nt >> 1][(nt & 1) * 2]);
        }
    }

    l0 += __shfl_xor_sync(0xffffffffu, l0, 1);
    l0 += __shfl_xor_sync(0xffffffffu, l0, 2);
    l1 += __shfl_xor_sync(0xffffffffu, l1, 1);
    l1 += __shfl_xor_sync(0xffffffffu, l1, 2);
    float inv0 = 1.f / l0, inv1 = 1.f / l1;

    float* sOut = (float*)(dynsm + 2u * QB);
    __syncthreads();
    if (br == 1) {
        float lamh = lam[h];
#pragma unroll
        for (int nt = 0; nt < 16; nt++) {
            int col = nt * 8 + la3 * 2;
            *(float2*)&sOut[(qr0 + lq) * 132 + col] =
                make_float2(lamh * inv0 * O[nt][0], lamh * inv0 * O[nt][1]);
            *(float2*)&sOut[(qr0 + lq + 8) * 132 + col] =
                make_float2(lamh * inv1 * O[nt][2], lamh * inv1 * O[nt][3]);
        }
    }
    __syncthreads();
    if (br == 0) {
        __half* ho = g_h + OFF_HO + ((size_t)(b * SSEQ + qt * 64)) * DM + h * HD;
#pragma unroll
        for (int nt = 0; nt < 16; nt++) {
            int col = nt * 8 + la3 * 2;
            float2 s0 = *(float2*)&sOut[(qr0 + lq) * 132 + col];
            float2 s1 = *(float2*)&sOut[(qr0 + lq + 8) * 132 + col];
            *(__half2*)&ho[(size_t)(qr0 + lq) * DM + col] =
                __floats2half2_rn(O[nt][0] * inv0 - s0.x, O[nt][1] * inv0 - s0.y);
            *(__half2*)&ho[(size_t)(qr0 + lq + 8) * DM + col] =
                __floats2half2_rn(O[nt][2] * inv1 - s1.x, O[nt][3] * inv1 - s1.y);
        }
    }
}

// ===========================================================================
// One-shot fp32->fp16 of x + 6 weights (dst contiguous in g_h).
// ===========================================================================
#define X_N4 (PROJ_SZ / 4)             // 2097152
#define W_N4 (W_SZ / 4)                // 1048576
#define ALL_N4 (X_N4 + 6 * W_N4)       // 8388608

__global__ void __launch_bounds__(256) f2h_all(
    const float* __restrict__ x,
    const float* __restrict__ w0, const float* __restrict__ w1,
    const float* __restrict__ w2, const float* __restrict__ w3,
    const float* __restrict__ w4, const float* __restrict__ w5)
{
    size_t i = (size_t)blockIdx.x * 256 + threadIdx.x;
    const float* src;
    size_t li;
    if (i < X_N4) { src = x; li = i; }
    else {
        size_t j = i - X_N4;
        int s = (int)(j / W_N4);
        li = j - (size_t)s * W_N4;
        src = (s == 0) ? w0 : (s == 1) ? w1 : (s == 2) ? w2
            : (s == 3) ? w3 : (s == 4) ? w4 : w5;
    }
    float4 v = ((const float4*)src)[li];
    __half2* d = (__half2*)g_h;
    d[2 * i]     = __floats2half2_rn(v.x, v.y);
    d[2 * i + 1] = __floats2half2_rn(v.z, v.w);
}

// ===========================================================================
extern "C" void kernel_launch(void* const* d_in, const int* in_sizes, int n_in,
                              void* d_out, int out_size)
{
    const float* x   = (const float*)d_in[0];
    const float* wq1 = (const float*)d_in[1];
    const float* wk1 = (const float*)d_in[2];
    const float* wq2 = (const float*)d_in[3];
    const float* wk2 = (const float*)d_in[4];
    const float* wv  = (const float*)d_in[5];
    const float* wo  = (const float*)d_in[6];
    const float* lam = (const float*)d_in[7];
    float* out = (float*)d_out;

    cudaFuncSetAttribute(gemm_proj, cudaFuncAttributeMaxDynamicSharedMemorySize, HSMEM);
    cudaFuncSetAttribute(gemm_out,  cudaFuncAttributeMaxDynamicSharedMemorySize, HSMEM);
    cudaFuncSetAttribute(flash_diff, cudaFuncAttributeMaxDynamicSharedMemorySize, FL_SMEM);

    dim3 blk(256);

    // 0) single conversion pass: x + 6 weights
    f2h_all<<<ALL_N4 / 256, blk>>>(x, wq1, wk1, wq2, wk2, wv, wo);

    // 1) all five projections in ONE launch (z = weight idx; V transposed)
    gemm_proj<<<dim3(16, 32, 5), blk, HSMEM>>>();

    // 2) fused differential flash attention -> HO (half)
    flash_diff<<<dim3(SSEQ / 64, BB * NH), blk, FL_SMEM>>>(lam);

    // 3) output projection -> d_out (float)
    gemm_out<<<dim3(16, 32, 1), blk, HSMEM>>>(out);
}